// round 4
// baseline (speedup 1.0000x reference)
#include <cuda_runtime.h>
#include <math.h>
#include <stdint.h>

#define BBATCH 2
#define SSEQ 2048
#define EEMB 1024
#define HHEADS 16
#define DKK 64
#define BHS (BBATCH*HHEADS*SSEQ)

// Scratch (tf32-rounded values, written by projection epilogues)
__device__ float g_k[BHS*DKK];
__device__ float g_v[BHS*DKK];
__device__ float g_q[BHS*DKK];

// ---------------- helpers ----------------
__device__ __forceinline__ float to_tf32(float x){
    float r; asm("cvt.rna.tf32.f32 %0, %1;" : "=f"(r) : "f"(x)); return r;
}
__device__ __forceinline__ void rnd4(float4& v){
    v.x = to_tf32(v.x); v.y = to_tf32(v.y); v.z = to_tf32(v.z); v.w = to_tf32(v.w);
}
__device__ __forceinline__ void mma8(float* d,
                                     uint32_t a0, uint32_t a1, uint32_t a2, uint32_t a3,
                                     uint32_t b0, uint32_t b1)
{
    asm volatile("mma.sync.aligned.m16n8k8.row.col.f32.tf32.tf32.f32 "
        "{%0,%1,%2,%3}, {%4,%5,%6,%7}, {%8,%9}, {%0,%1,%2,%3};"
        : "+f"(d[0]), "+f"(d[1]), "+f"(d[2]), "+f"(d[3])
        : "r"(a0), "r"(a1), "r"(a2), "r"(a3), "r"(b0), "r"(b1));
}
#define U(x) __float_as_uint(x)
__device__ __forceinline__ void mma8f(float* d, const float4& a, float b0, float b1){
    mma8(d, U(a.x), U(a.y), U(a.z), U(a.w), U(b0), U(b1));
}

// =====================================================================
// Projection GEMM: C[m,n] = sum_e A[m,e]*W[n,e]. M=4096, N=1024, K=1024.
// CTA 128x128, 8 warps (4x2), warp 32x64, BK=32, double-buffered permuted smem.
// Fragment layouts (per 32-k chunk):
//   Ap[(g*4+s)*32 + lane] : float4 a-frag (g=row>>4 of 8, s=k-step of 4)
//   Bp[(tn*2+sp)*32+lane] : float4 = b-frags for k-steps 2sp,2sp+1 (tn of 16)
// Epilogue writes tf32-rounded values; mode 2 applies cos(v+theta)*0.125.
// =====================================================================
#define PJ_SMEM (16384*4)   // 64KB: Ap0,Ap1,Bp0,Bp1 each 4096 floats

__global__ __launch_bounds__(256, 2)
void proj_mma(const float* __restrict__ A, const float* __restrict__ W,
              const float* __restrict__ theta, float* __restrict__ dst, int mode)
{
    extern __shared__ float sm[];
    // Ap buffers at 0,4096; Bp at 8192,12288

    const int tid = threadIdx.x;
    const int wid = tid >> 5, lane = tid & 31;
    const int gid = lane >> 2, tig = lane & 3;
    const int wm = wid >> 1, wn = wid & 1;
    const int row0 = blockIdx.y * 128;
    const int col0 = blockIdx.x * 128;

    // staging indices (4 float4 per thread per chunk, each for A and W)
    int aidx[4], bidx[4], src[4];
    #pragma unroll
    for (int i = 0; i < 4; i++) {
        int f = tid + i * 256;
        int r = f >> 3, c = (f & 7) << 2;
        src[i] = r * EEMB + c;
        int g = r >> 4, row16 = r & 15, eb = (row16 >> 3) & 1, ga = row16 & 7;
        int s = c >> 3, hi = (c >> 2) & 1;
        aidx[i] = (((g * 4 + s) * 32 + ga * 4) << 2) + (eb + 2 * hi);
        int tn = r >> 3, gb = r & 7, sp = s >> 1, so = s & 1;
        bidx[i] = (((tn * 2 + sp) * 32 + gb * 4) << 2) + (2 * so + hi);
    }

    float acc[2][8][4];
    #pragma unroll
    for (int g2 = 0; g2 < 2; g2++)
        #pragma unroll
        for (int tn = 0; tn < 8; tn++)
            #pragma unroll
            for (int e = 0; e < 4; e++) acc[g2][tn][e] = 0.f;

    const float* Ab = A + (size_t)row0 * EEMB;
    const float* Wb = W + (size_t)col0 * EEMB;

    float4 apf[4], bpf[4];
    #pragma unroll
    for (int i = 0; i < 4; i++) {
        apf[i] = *(const float4*)(Ab + src[i]);
        bpf[i] = *(const float4*)(Wb + src[i]);
    }
    #pragma unroll
    for (int i = 0; i < 4; i++) {
        rnd4(apf[i]); rnd4(bpf[i]);
        float* ap = sm + aidx[i];
        ap[0] = apf[i].x; ap[4] = apf[i].y; ap[8] = apf[i].z; ap[12] = apf[i].w;
        float* bp = sm + 8192 + bidx[i];
        bp[0] = bpf[i].x; bp[4] = bpf[i].y; bp[8] = bpf[i].z; bp[12] = bpf[i].w;
    }
    __syncthreads();

    #pragma unroll 1
    for (int ch = 0; ch < 32; ch++) {
        const int cur = ch & 1;
        if (ch < 31) {
            const int k0 = (ch + 1) * 32;
            #pragma unroll
            for (int i = 0; i < 4; i++) {
                apf[i] = *(const float4*)(Ab + src[i] + k0);
                bpf[i] = *(const float4*)(Wb + src[i] + k0);
            }
        }
        const float* Ap = sm + cur * 4096;
        const float* Bp = sm + 8192 + cur * 4096;
        #pragma unroll
        for (int sp = 0; sp < 2; sp++) {
            float4 aF[2][2];
            #pragma unroll
            for (int g2 = 0; g2 < 2; g2++)
                #pragma unroll
                for (int so = 0; so < 2; so++)
                    aF[g2][so] = *(const float4*)(Ap + ((((2*wm+g2)*4 + 2*sp+so)*32 + lane) << 2));
            #pragma unroll
            for (int tn = 0; tn < 8; tn++) {
                float4 bb = *(const float4*)(Bp + ((((wn*8+tn)*2 + sp)*32 + lane) << 2));
                #pragma unroll
                for (int g2 = 0; g2 < 2; g2++) {
                    mma8f(acc[g2][tn], aF[g2][0], bb.x, bb.y);
                    mma8f(acc[g2][tn], aF[g2][1], bb.z, bb.w);
                }
            }
        }
        if (ch < 31) {
            float* Apn = sm + (cur ^ 1) * 4096;
            float* Bpn = sm + 8192 + (cur ^ 1) * 4096;
            #pragma unroll
            for (int i = 0; i < 4; i++) {
                rnd4(apf[i]); rnd4(bpf[i]);
                float* ap = Apn + aidx[i];
                ap[0] = apf[i].x; ap[4] = apf[i].y; ap[8] = apf[i].z; ap[12] = apf[i].w;
                float* bp = Bpn + bidx[i];
                bp[0] = bpf[i].x; bp[4] = bpf[i].y; bp[8] = bpf[i].z; bp[12] = bpf[i].w;
            }
        }
        __syncthreads();
    }

    // epilogue: tf32-rounded scatter to [bh][s][d]
    #pragma unroll
    for (int g2 = 0; g2 < 2; g2++) {
        #pragma unroll
        for (int tn = 0; tn < 8; tn++) {
            #pragma unroll
            for (int e = 0; e < 4; e++) {
                int m = row0 + wm * 32 + g2 * 16 + gid + (e >= 2 ? 8 : 0);
                int n = col0 + wn * 64 + tn * 8 + 2 * tig + (e & 1);
                int b = m >> 11, s = m & (SSEQ - 1);
                int h = n >> 6,  d = n & (DKK - 1);
                float v = acc[g2][tn][e];
                if (mode == 2) v = cosf(v + __ldg(&theta[d])) * 0.125f;
                dst[((size_t)(b * HHEADS + h) * SSEQ + s) * DKK + d] = to_tf32(v);
            }
        }
    }
}

// =====================================================================
// Attention: CTA = 128 queries x 1 head, 8 warps, warp = 16q x 64keys.
// Exact softmax w/o max subtraction (|score| <= ~4). P kept in registers
// via quad shuffles. K/V double-buffered permuted smem, 1 sync/tile.
// smem floats: Qp[0,8192) ; buf b: Kp at 8192+b*8192, Vp at +4096.
// =====================================================================
#define AT_SMEM (24576*4)   // 96KB

__global__ __launch_bounds__(256, 2)
void attn_mma(float* __restrict__ out)
{
    extern __shared__ float sm[];
    const int tid = threadIdx.x;
    const int wid = tid >> 5, lane = tid & 31;
    const int gid = lane >> 2, tig = lane & 3;
    const int bh = blockIdx.y;
    const int s0 = blockIdx.x * 128;

    const float* qbase = g_q + ((size_t)bh * SSEQ + s0) * DKK;
    const float* kbase = g_k + (size_t)bh * SSEQ * DKK;
    const float* vbase = g_v + (size_t)bh * SSEQ * DKK;

    // ---- stage Q (once): a-frag layout Qp[(g*8+s)*32+lane] float4 ----
    #pragma unroll
    for (int i = 0; i < 8; i++) {
        int f = tid + i * 256;
        int r = f >> 4, c = (f & 15) << 2;
        float4 v = *(const float4*)(qbase + r * DKK + c);
        int g = r >> 4, row16 = r & 15, eb = (row16 >> 3) & 1, ga = row16 & 7;
        int s = c >> 3, hi = (c >> 2) & 1;
        float* qp = sm + (((g * 8 + s) * 32 + ga * 4) << 2) + (eb + 2 * hi);
        qp[0] = v.x; qp[4] = v.y; qp[8] = v.z; qp[12] = v.w;
    }

    // ---- staging indices for K/V (4 float4/thread/tile each) ----
    int kidx[4], vidx[4], src[4];
    #pragma unroll
    for (int i = 0; i < 4; i++) {
        int f = tid + i * 256;
        int r = f >> 4, c = (f & 15) << 2;
        src[i] = r * DKK + c;
        int tn = r >> 3, gk = r & 7;
        int s = c >> 3, sp = s >> 1, so = s & 1, hi = (c >> 2) & 1;
        kidx[i] = (((tn * 4 + sp) * 32 + gk * 4) << 2) + (2 * so + hi);
        int ks = r >> 3, kp = ks >> 1, ko = ks & 1, tv = r & 3, hi2 = (r >> 2) & 1;
        int dn = c >> 3, gv = c & 7;
        vidx[i] = (((dn * 4 + kp) * 32 + gv * 4 + tv) << 2) + (2 * ko + hi2);
    }

    // ---- prefetch + stage tile 0 ----
    float4 kpf[4], vpf[4];
    #pragma unroll
    for (int i = 0; i < 4; i++) {
        kpf[i] = *(const float4*)(kbase + src[i]);
        vpf[i] = *(const float4*)(vbase + src[i]);
    }
    #pragma unroll
    for (int i = 0; i < 4; i++) {
        float* kp = sm + 8192 + kidx[i];
        kp[0] = kpf[i].x; kp[4] = kpf[i].y; kp[8] = kpf[i].z; kp[12] = kpf[i].w;
        float* vp = sm + 8192 + 4096 + vidx[i];
        vp[0] = vpf[i].x; vp[16] = vpf[i].y; vp[32] = vpf[i].z; vp[48] = vpf[i].w;
    }
    __syncthreads();

    float oacc[8][4];
    #pragma unroll
    for (int dn = 0; dn < 8; dn++)
        #pragma unroll
        for (int e = 0; e < 4; e++) oacc[dn][e] = 0.f;
    float lsum0 = 0.f, lsum1 = 0.f;

    const int srcA = (lane & ~3) | (tig >> 1);
    const int srcB = srcA + 2;
    const bool odd = (tig & 1);

    #pragma unroll 1
    for (int t = 0; t < 32; t++) {
        const int cur = t & 1;
        const float* Kp = sm + 8192 + cur * 8192;
        const float* Vp = Kp + 4096;

        if (t < 31) {
            const int off = (t + 1) * 64 * DKK;
            #pragma unroll
            for (int i = 0; i < 4; i++)
                kpf[i] = *(const float4*)(kbase + off + src[i]);
        }

        // ---- S = Q @ K^T (16q x 64 keys per warp) ----
        float sacc[8][4];
        #pragma unroll
        for (int tn = 0; tn < 8; tn++)
            #pragma unroll
            for (int e = 0; e < 4; e++) sacc[tn][e] = 0.f;

        #pragma unroll
        for (int sp = 0; sp < 4; sp++) {
            float4 aL = *(const float4*)(sm + (((wid * 8 + 2*sp    ) * 32 + lane) << 2));
            float4 aH = *(const float4*)(sm + (((wid * 8 + 2*sp + 1) * 32 + lane) << 2));
            #pragma unroll
            for (int tn = 0; tn < 8; tn++) {
                float4 kb = *(const float4*)(Kp + (((tn * 4 + sp) * 32 + lane) << 2));
                mma8f(sacc[tn], aL, kb.x, kb.y);
                mma8f(sacc[tn], aH, kb.z, kb.w);
            }
        }

        // ---- P = exp(S), row sums ----
        #pragma unroll
        for (int tn = 0; tn < 8; tn++) {
            float p0 = to_tf32(__expf(sacc[tn][0]));
            float p1 = to_tf32(__expf(sacc[tn][1]));
            float p2 = to_tf32(__expf(sacc[tn][2]));
            float p3 = to_tf32(__expf(sacc[tn][3]));
            lsum0 += p0 + p1; lsum1 += p2 + p3;
            sacc[tn][0] = p0; sacc[tn][1] = p1; sacc[tn][2] = p2; sacc[tn][3] = p3;
        }

        if (t < 31) {
            const int off = (t + 1) * 64 * DKK;
            #pragma unroll
            for (int i = 0; i < 4; i++)
                vpf[i] = *(const float4*)(vbase + off + src[i]);
        }

        // ---- O += P @ V (P in registers via quad shuffles) ----
        #pragma unroll
        for (int kp = 0; kp < 4; kp++) {
            float4 aA, aB;
            {
                const float* p = sacc[2 * kp];
                float v00 = __shfl_sync(0xffffffffu, p[0], srcA);
                float v01 = __shfl_sync(0xffffffffu, p[1], srcA);
                float v10 = __shfl_sync(0xffffffffu, p[2], srcA);
                float v11 = __shfl_sync(0xffffffffu, p[3], srcA);
                float v20 = __shfl_sync(0xffffffffu, p[0], srcB);
                float v21 = __shfl_sync(0xffffffffu, p[1], srcB);
                float v30 = __shfl_sync(0xffffffffu, p[2], srcB);
                float v31 = __shfl_sync(0xffffffffu, p[3], srcB);
                aA.x = odd ? v01 : v00; aA.y = odd ? v11 : v10;
                aA.z = odd ? v21 : v20; aA.w = odd ? v31 : v30;
            }
            {
                const float* p = sacc[2 * kp + 1];
                float v00 = __shfl_sync(0xffffffffu, p[0], srcA);
                float v01 = __shfl_sync(0xffffffffu, p[1], srcA);
                float v10 = __shfl_sync(0xffffffffu, p[2], srcA);
                float v11 = __shfl_sync(0xffffffffu, p[3], srcA);
                float v20 = __shfl_sync(0xffffffffu, p[0], srcB);
                float v21 = __shfl_sync(0xffffffffu, p[1], srcB);
                float v30 = __shfl_sync(0xffffffffu, p[2], srcB);
                float v31 = __shfl_sync(0xffffffffu, p[3], srcB);
                aB.x = odd ? v01 : v00; aB.y = odd ? v11 : v10;
                aB.z = odd ? v21 : v20; aB.w = odd ? v31 : v30;
            }
            #pragma unroll
            for (int dn = 0; dn < 8; dn++) {
                float4 vb = *(const float4*)(Vp + (((dn * 4 + kp) * 32 + lane) << 2));
                mma8f(oacc[dn], aA, vb.x, vb.y);
                mma8f(oacc[dn], aB, vb.z, vb.w);
            }
        }

        if (t < 31) {
            float* Kn = sm + 8192 + (cur ^ 1) * 8192;
            float* Vn = Kn + 4096;
            #pragma unroll
            for (int i = 0; i < 4; i++) {
                float* kp = Kn + kidx[i];
                kp[0] = kpf[i].x; kp[4] = kpf[i].y; kp[8] = kpf[i].z; kp[12] = kpf[i].w;
                float* vp = Vn + vidx[i];
                vp[0] = vpf[i].x; vp[16] = vpf[i].y; vp[32] = vpf[i].z; vp[48] = vpf[i].w;
            }
        }
        __syncthreads();
    }

    // ---- finalize: quad-reduce row sums (all lanes get full sum) ----
    lsum0 += __shfl_xor_sync(0xffffffffu, lsum0, 1);
    lsum0 += __shfl_xor_sync(0xffffffffu, lsum0, 2);
    lsum1 += __shfl_xor_sync(0xffffffffu, lsum1, 1);
    lsum1 += __shfl_xor_sync(0xffffffffu, lsum1, 2);
    const float inv0 = 1.f / lsum0;
    const float inv1 = 1.f / lsum1;

    const int b = bh >> 4, h = bh & (HHEADS - 1);
    float* o0 = out + ((size_t)b * SSEQ + s0 + wid * 16 + gid) * EEMB + h * DKK;
    float* o1 = o0 + 8 * EEMB;
    #pragma unroll
    for (int dn = 0; dn < 8; dn++) {
        int c = dn * 8 + 2 * tig;
        *(float2*)(o0 + c) = make_float2(oacc[dn][0] * inv0, oacc[dn][1] * inv0);
        *(float2*)(o1 + c) = make_float2(oacc[dn][2] * inv1, oacc[dn][3] * inv1);
    }
}

// ===================== launch =====================
extern "C" void kernel_launch(void* const* d_in, const int* in_sizes, int n_in,
                              void* d_out, int out_size)
{
    const float* x     = (const float*)d_in[0];
    const float* Wk    = (const float*)d_in[1];
    const float* Wv    = (const float*)d_in[2];
    const float* Wq    = (const float*)d_in[3];
    const float* theta = (const float*)d_in[4];
    float* out = (float*)d_out;

    float *gk, *gv, *gq;
    cudaGetSymbolAddress((void**)&gk, g_k);
    cudaGetSymbolAddress((void**)&gv, g_v);
    cudaGetSymbolAddress((void**)&gq, g_q);

    cudaFuncSetAttribute(proj_mma, cudaFuncAttributeMaxDynamicSharedMemorySize, PJ_SMEM);
    cudaFuncSetAttribute(attn_mma, cudaFuncAttributeMaxDynamicSharedMemorySize, AT_SMEM);

    dim3 gp(EEMB / 128, (BBATCH * SSEQ) / 128);   // (8, 32)
    proj_mma<<<gp, 256, PJ_SMEM>>>(x, Wk, theta, gk, 0);
    proj_mma<<<gp, 256, PJ_SMEM>>>(x, Wv, theta, gv, 1);
    proj_mma<<<gp, 256, PJ_SMEM>>>(x, Wq, theta, gq, 2);

    dim3 ga(SSEQ / 128, BBATCH * HHEADS);          // (16, 32)
    attn_mma<<<ga, 256, AT_SMEM>>>(out);
}

// round 5
// speedup vs baseline: 1.7146x; 1.7146x over previous
#include <cuda_runtime.h>
#include <math.h>
#include <stdint.h>

#define BBATCH 2
#define SSEQ 2048
#define EEMB 1024
#define HHEADS 16
#define DKK 64
#define BHS (BBATCH*HHEADS*SSEQ)

// Scratch
__device__ float g_xr[4096*1024];          // tf32-rounded x
__device__ float g_wi[3][1024*1024];       // W rounded + b-frag interleaved: [qg64][n1024][tig4][comp4]
__device__ float g_k[BHS*DKK];             // interleaved: [bh][qg4][s2048][tig4][comp4]
__device__ float g_v[BHS*DKK];             // natural [bh][s][d], tf32-rounded
__device__ float g_q[BHS*DKK];             // natural [bh][s][d], tf32-rounded

// ---------------- helpers ----------------
__device__ __forceinline__ float to_tf32(float x){
    float r; asm("cvt.rna.tf32.f32 %0, %1;" : "=f"(r) : "f"(x)); return r;
}
__device__ __forceinline__ void rnd4(float4& v){
    v.x = to_tf32(v.x); v.y = to_tf32(v.y); v.z = to_tf32(v.z); v.w = to_tf32(v.w);
}
__device__ __forceinline__ void mma8(float* d,
                                     uint32_t a0, uint32_t a1, uint32_t a2, uint32_t a3,
                                     uint32_t b0, uint32_t b1)
{
    asm volatile("mma.sync.aligned.m16n8k8.row.col.f32.tf32.tf32.f32 "
        "{%0,%1,%2,%3}, {%4,%5,%6,%7}, {%8,%9}, {%0,%1,%2,%3};"
        : "+f"(d[0]), "+f"(d[1]), "+f"(d[2]), "+f"(d[3])
        : "r"(a0), "r"(a1), "r"(a2), "r"(a3), "r"(b0), "r"(b1));
}
#define U(x) __float_as_uint(x)
__device__ __forceinline__ void mma8f(float* d, const float4& a, float b0, float b1){
    mma8(d, U(a.x), U(a.y), U(a.z), U(a.w), U(b0), U(b1));
}
__device__ __forceinline__ uint32_t smem_u32(const void* p){
    uint32_t a;
    asm("{ .reg .u64 t; cvta.to.shared.u64 t, %1; cvt.u32.u64 %0, t; }" : "=r"(a) : "l"(p));
    return a;
}
#define CP16(dst, src) asm volatile("cp.async.cg.shared.global [%0], [%1], 16;" :: "r"(dst), "l"(src))
#define CP_COMMIT()    asm volatile("cp.async.commit_group;" ::: "memory")
#define CP_WAIT0()     asm volatile("cp.async.wait_group 0;" ::: "memory")
#define CP_WAIT1()     asm volatile("cp.async.wait_group 1;" ::: "memory")

// =====================================================================
// Prep: round x -> g_xr ; round + interleave W -> g_wi[t]
// W element [n][k] -> g_wi[t][ ((k>>4)*1024 + n)*16 + (k&3)*4 + ((k>>2)&3) ]
// =====================================================================
__global__ __launch_bounds__(256)
void prep_kernel(const float* __restrict__ x, const float* __restrict__ Wk,
                 const float* __restrict__ Wv, const float* __restrict__ Wq)
{
    const int gi = blockIdx.x * 256 + threadIdx.x;
    if (blockIdx.y == 0) {
        if (gi < 4096*1024/4) {
            float4 v = ((const float4*)x)[gi];
            rnd4(v);
            ((float4*)g_xr)[gi] = v;
        }
    } else {
        if (gi < 1024*1024/4) {
            const float* W = (blockIdx.y == 1) ? Wk : (blockIdx.y == 2) ? Wv : Wq;
            float* dst = g_wi[blockIdx.y - 1];
            float4 v = ((const float4*)W)[gi];
            rnd4(v);
            int n = gi >> 8, j = gi & 255;            // j = float4 index in row (k = 4j..4j+3)
            int base = ((j >> 2) * 1024 + n) * 16 + (j & 3);
            dst[base     ] = v.x;
            dst[base +  4] = v.y;
            dst[base +  8] = v.z;
            dst[base + 12] = v.w;
        }
    }
}

// =====================================================================
// Projection: C[m,n] = sum_e xr[m,e]*W[n,e]. CTA 128x128, 8 warps (4x2),
// warp 32x64, BK=32, cp.async double-buffered.
// smem floats: As[2] @ 0/4608 (128 rows x 36); Wi[2] @ 9216/13312 (2qg x 128 x 16)
// mode 0: K (interleaved gmem), 1: V (natural), 2: Q=cos(v+theta)*0.125 (natural)
// =====================================================================
#define PJ_SMEM (17408*4)

__global__ __launch_bounds__(256, 2)
void proj_mma(const float* __restrict__ theta, float* __restrict__ dst,
              const float* __restrict__ Wint, int mode)
{
    extern __shared__ float sm[];
    const uint32_t sb = smem_u32(sm);
    const int tid = threadIdx.x;
    const int wid = tid >> 5, lane = tid & 31;
    const int gid = lane >> 2, tig = lane & 3;
    const int wm = wid >> 1, wn = wid & 1;
    const int row0 = blockIdx.y * 128;
    const int col0 = blockIdx.x * 128;

    float acc[2][8][4];
    #pragma unroll
    for (int i = 0; i < 2; i++)
        #pragma unroll
        for (int j = 0; j < 8; j++)
            #pragma unroll
            for (int e = 0; e < 4; e++) acc[i][j][e] = 0.f;

    const float* Ab = g_xr + (size_t)row0 * EEMB;

    // cp.async issue for chunk ch into buffer b
    auto issue = [&](int ch, int b) {
        const int k0 = ch * 32;
        uint32_t adst = sb + (b * 4608) * 4;
        uint32_t wdst = sb + (9216 + b * 4096) * 4;
        #pragma unroll
        for (int i = 0; i < 4; i++) {                 // A: 1024 chunks of 16B
            int ca = tid + i * 256;
            int r = ca >> 3, seg = ca & 7;
            CP16(adst + (r * 36 + seg * 4) * 4, Ab + (size_t)r * EEMB + k0 + seg * 4);
        }
        const float* Wb = Wint + (size_t)(ch * 2) * 1024 * 16 + (size_t)col0 * 16;
        #pragma unroll
        for (int i = 0; i < 4; i++) {                 // W: 1024 chunks of 16B
            int cw = tid + i * 256;
            int qg = cw >> 9, rem = cw & 511;
            int n = rem >> 2, ts = rem & 3;
            CP16(wdst + (qg * 2048 + n * 16 + ts * 4) * 4,
                 Wb + (size_t)qg * 1024 * 16 + n * 16 + ts * 4);
        }
        CP_COMMIT();
    };

    issue(0, 0);
    #pragma unroll 1
    for (int ch = 0; ch < 32; ch++) {
        const int buf = ch & 1;
        if (ch < 31) issue(ch + 1, buf ^ 1);
        if (ch < 31) { CP_WAIT1(); } else { CP_WAIT0(); }
        __syncthreads();

        const float* As = sm + buf * 4608;
        const float* Wi = sm + 9216 + buf * 4096;
        #pragma unroll
        for (int qg = 0; qg < 2; qg++) {
            float4 af0[2], af1[2];
            #pragma unroll
            for (int tm = 0; tm < 2; tm++) {
                const float* a0 = As + (wm * 32 + tm * 16 + gid) * 36 + qg * 16 + tig;
                const float* a8 = a0 + 8 * 36;
                af0[tm] = make_float4(a0[0], a8[0], a0[4], a8[4]);
                af1[tm] = make_float4(a0[8], a8[8], a0[12], a8[12]);
            }
            #pragma unroll
            for (int tn = 0; tn < 8; tn++) {
                float4 wb = *(const float4*)(Wi + qg * 2048 + (wn * 64 + tn * 8 + gid) * 16 + tig * 4);
                #pragma unroll
                for (int tm = 0; tm < 2; tm++) {
                    mma8f(acc[tm][tn], af0[tm], wb.x, wb.y);
                    mma8f(acc[tm][tn], af1[tm], wb.z, wb.w);
                }
            }
        }
        __syncthreads();
    }

    // epilogue scatter (tf32-rounded)
    #pragma unroll
    for (int tm = 0; tm < 2; tm++) {
        #pragma unroll
        for (int tn = 0; tn < 8; tn++) {
            #pragma unroll
            for (int e = 0; e < 4; e++) {
                int m = row0 + wm * 32 + tm * 16 + gid + (e >= 2 ? 8 : 0);
                int n = col0 + wn * 64 + tn * 8 + 2 * tig + (e & 1);
                int b = m >> 11, s = m & (SSEQ - 1);
                int h = n >> 6,  d = n & (DKK - 1);
                int bh = b * HHEADS + h;
                float v = acc[tm][tn][e];
                if (mode == 2) v = cosf(v + __ldg(&theta[d])) * 0.125f;
                v = to_tf32(v);
                size_t idx;
                if (mode == 0)
                    idx = ((size_t)(bh * 4 + (d >> 4)) * SSEQ + s) * 16 + (d & 3) * 4 + ((d >> 2) & 3);
                else
                    idx = ((size_t)bh * SSEQ + s) * DKK + d;
                dst[idx] = v;
            }
        }
    }
}

// =====================================================================
// Attention: CTA = 128q x 1 head, 8 warps, warp = 16q x 64keys x 64d.
// Q frags in regs. K interleaved smem (LDS.128 b-frags). V natural (stride 72).
// P via quad-shuffle transpose (no smem). Exact softmax, no max subtraction.
// smem floats: K[2] @ 0/4096 (4096 each); V[2] @ 8192/12800 (4608 each)
// =====================================================================
#define AT_SMEM (17408*4)

__global__ __launch_bounds__(256, 2)
void attn_mma(float* __restrict__ out)
{
    extern __shared__ float sm[];
    const uint32_t sb = smem_u32(sm);
    const int tid = threadIdx.x;
    const int wid = tid >> 5, lane = tid & 31;
    const int gid = lane >> 2, tig = lane & 3;
    const int bh = blockIdx.y;
    const int s0 = blockIdx.x * 128;

    // ---- Q fragments in registers (once) ----
    float4 qf[8];
    {
        const float* qb = g_q + ((size_t)bh * SSEQ + s0 + wid * 16) * DKK;
        #pragma unroll
        for (int m = 0; m < 8; m++) {
            int c = 8 * m + tig;
            qf[m] = make_float4(qb[gid * DKK + c],       qb[(gid + 8) * DKK + c],
                                qb[gid * DKK + c + 4],   qb[(gid + 8) * DKK + c + 4]);
        }
    }

    const float* kg = g_k + (size_t)bh * 4 * SSEQ * 16;
    const float* vg = g_v + (size_t)bh * SSEQ * DKK;

    auto issue = [&](int t, int b) {
        const int t0 = t * 64;
        uint32_t kdst = sb + (b * 4096) * 4;
        uint32_t vdst = sb + (8192 + b * 4608) * 4;
        #pragma unroll
        for (int i = 0; i < 4; i++) {                 // K: 1024 x 16B
            int ck = tid + i * 256;
            int qg = ck >> 8, rem = ck & 255;
            int key = rem >> 2, ts = rem & 3;
            CP16(kdst + (qg * 1024 + key * 16 + ts * 4) * 4,
                 kg + ((size_t)qg * SSEQ + t0 + key) * 16 + ts * 4);
        }
        #pragma unroll
        for (int i = 0; i < 4; i++) {                 // V: 1024 x 16B
            int cv = tid + i * 256;
            int row = cv >> 4, seg = cv & 15;
            CP16(vdst + (row * 72 + seg * 4) * 4,
                 vg + (size_t)(t0 + row) * DKK + seg * 4);
        }
        CP_COMMIT();
    };

    float oacc[8][4];
    #pragma unroll
    for (int dn = 0; dn < 8; dn++)
        #pragma unroll
        for (int e = 0; e < 4; e++) oacc[dn][e] = 0.f;
    float lsum0 = 0.f, lsum1 = 0.f;

    const int srcA = (lane & ~3) | (tig >> 1);
    const int srcB = srcA + 2;
    const bool odd = (tig & 1);

    issue(0, 0);
    #pragma unroll 1
    for (int t = 0; t < 32; t++) {
        const int buf = t & 1;
        if (t < 31) issue(t + 1, buf ^ 1);
        if (t < 31) { CP_WAIT1(); } else { CP_WAIT0(); }
        __syncthreads();

        const float* Kp = sm + buf * 4096;
        const float* Vp = sm + 8192 + buf * 4608;

        // ---- S = Q @ K^T ----
        float sacc[8][4];
        #pragma unroll
        for (int tn = 0; tn < 8; tn++)
            #pragma unroll
            for (int e = 0; e < 4; e++) sacc[tn][e] = 0.f;

        #pragma unroll
        for (int qg = 0; qg < 4; qg++) {
            #pragma unroll
            for (int tn = 0; tn < 8; tn++) {
                float4 kb = *(const float4*)(Kp + qg * 1024 + (tn * 8 + gid) * 16 + tig * 4);
                mma8f(sacc[tn], qf[2 * qg    ], kb.x, kb.y);
                mma8f(sacc[tn], qf[2 * qg + 1], kb.z, kb.w);
            }
        }

        // ---- P = exp(S), row sums ----
        #pragma unroll
        for (int tn = 0; tn < 8; tn++) {
            float p0 = to_tf32(__expf(sacc[tn][0]));
            float p1 = to_tf32(__expf(sacc[tn][1]));
            float p2 = to_tf32(__expf(sacc[tn][2]));
            float p3 = to_tf32(__expf(sacc[tn][3]));
            lsum0 += p0 + p1; lsum1 += p2 + p3;
            sacc[tn][0] = p0; sacc[tn][1] = p1; sacc[tn][2] = p2; sacc[tn][3] = p3;
        }

        // ---- O += P @ V  (P via quad shuffles) ----
        #pragma unroll
        for (int j = 0; j < 8; j++) {
            const float* p = sacc[j];
            float v00 = __shfl_sync(0xffffffffu, p[0], srcA);
            float v01 = __shfl_sync(0xffffffffu, p[1], srcA);
            float v10 = __shfl_sync(0xffffffffu, p[2], srcA);
            float v11 = __shfl_sync(0xffffffffu, p[3], srcA);
            float v20 = __shfl_sync(0xffffffffu, p[0], srcB);
            float v21 = __shfl_sync(0xffffffffu, p[1], srcB);
            float v30 = __shfl_sync(0xffffffffu, p[2], srcB);
            float v31 = __shfl_sync(0xffffffffu, p[3], srcB);
            float4 aA;
            aA.x = odd ? v01 : v00; aA.y = odd ? v11 : v10;
            aA.z = odd ? v21 : v20; aA.w = odd ? v31 : v30;

            const float* v0r = Vp + (8 * j + tig) * 72;
            const float* v4r = v0r + 4 * 72;
            #pragma unroll
            for (int dn = 0; dn < 8; dn++) {
                int d = dn * 8 + gid;
                mma8f(oacc[dn], aA, v0r[d], v4r[d]);
            }
        }
        __syncthreads();
    }

    // ---- finalize l and write out ----
    lsum0 += __shfl_xor_sync(0xffffffffu, lsum0, 1);
    lsum0 += __shfl_xor_sync(0xffffffffu, lsum0, 2);
    lsum1 += __shfl_xor_sync(0xffffffffu, lsum1, 1);
    lsum1 += __shfl_xor_sync(0xffffffffu, lsum1, 2);
    const float inv0 = 1.f / lsum0;
    const float inv1 = 1.f / lsum1;

    const int b = bh >> 4, h = bh & (HHEADS - 1);
    float* o0 = out + ((size_t)b * SSEQ + s0 + wid * 16 + gid) * EEMB + h * DKK;
    float* o1 = o0 + 8 * EEMB;
    #pragma unroll
    for (int dn = 0; dn < 8; dn++) {
        int c = dn * 8 + 2 * tig;
        *(float2*)(o0 + c) = make_float2(oacc[dn][0] * inv0, oacc[dn][1] * inv0);
        *(float2*)(o1 + c) = make_float2(oacc[dn][2] * inv1, oacc[dn][3] * inv1);
    }
}

// ===================== launch =====================
extern "C" void kernel_launch(void* const* d_in, const int* in_sizes, int n_in,
                              void* d_out, int out_size)
{
    const float* x     = (const float*)d_in[0];
    const float* Wk    = (const float*)d_in[1];
    const float* Wv    = (const float*)d_in[2];
    const float* Wq    = (const float*)d_in[3];
    const float* theta = (const float*)d_in[4];
    float* out = (float*)d_out;

    float *gk, *gv, *gq, *gwi;
    cudaGetSymbolAddress((void**)&gk,  g_k);
    cudaGetSymbolAddress((void**)&gv,  g_v);
    cudaGetSymbolAddress((void**)&gq,  g_q);
    cudaGetSymbolAddress((void**)&gwi, g_wi);

    cudaFuncSetAttribute(proj_mma, cudaFuncAttributeMaxDynamicSharedMemorySize, PJ_SMEM);
    cudaFuncSetAttribute(attn_mma, cudaFuncAttributeMaxDynamicSharedMemorySize, AT_SMEM);

    prep_kernel<<<dim3(4096, 4), 256>>>(x, Wk, Wv, Wq);

    dim3 gp(EEMB / 128, (BBATCH * SSEQ) / 128);   // (8, 32)
    proj_mma<<<gp, 256, PJ_SMEM>>>(theta, gk, gwi,               0);
    proj_mma<<<gp, 256, PJ_SMEM>>>(theta, gv, gwi + 1024*1024,   1);
    proj_mma<<<gp, 256, PJ_SMEM>>>(theta, gq, gwi + 2*1024*1024, 2);

    dim3 ga(SSEQ / 128, BBATCH * HHEADS);          // (16, 32)
    attn_mma<<<ga, 256, AT_SMEM>>>(out);
}

// round 6
// speedup vs baseline: 1.8640x; 1.0872x over previous
#include <cuda_runtime.h>
#include <math.h>
#include <stdint.h>

#define BBATCH 2
#define SSEQ 2048
#define EEMB 1024
#define HHEADS 16
#define DKK 64
#define BHS (BBATCH*HHEADS*SSEQ)

// Scratch
__device__ float g_xi[4096*1024];      // x: a-frag interleave [m>>4][k>>3][lane32][comp4]
__device__ float g_wi[3][1024*1024];   // W: b-frag interleave [k>>4][n>>3][lane32][comp4]
__device__ float g_k[BHS*DKK];         // K: [bh][tile][qg4][key>>3][lane32][comp4]
__device__ float g_v[BHS*DKK];         // V: [bh][tile][j8][dnp4][lane32][comp4]
__device__ float g_q[BHS*DKK];         // Q: natural [bh][s][d]

// ---------------- helpers ----------------
__device__ __forceinline__ float to_tf32(float x){
    float r; asm("cvt.rna.tf32.f32 %0, %1;" : "=f"(r) : "f"(x)); return r;
}
__device__ __forceinline__ void rnd4(float4& v){
    v.x = to_tf32(v.x); v.y = to_tf32(v.y); v.z = to_tf32(v.z); v.w = to_tf32(v.w);
}
__device__ __forceinline__ void mma8(float* d,
                                     uint32_t a0, uint32_t a1, uint32_t a2, uint32_t a3,
                                     uint32_t b0, uint32_t b1)
{
    asm volatile("mma.sync.aligned.m16n8k8.row.col.f32.tf32.tf32.f32 "
        "{%0,%1,%2,%3}, {%4,%5,%6,%7}, {%8,%9}, {%0,%1,%2,%3};"
        : "+f"(d[0]), "+f"(d[1]), "+f"(d[2]), "+f"(d[3])
        : "r"(a0), "r"(a1), "r"(a2), "r"(a3), "r"(b0), "r"(b1));
}
#define U(x) __float_as_uint(x)
__device__ __forceinline__ void mma8f(float* d, const float4& a, float b0, float b1){
    mma8(d, U(a.x), U(a.y), U(a.z), U(a.w), U(b0), U(b1));
}
__device__ __forceinline__ uint32_t smem_u32(const void* p){
    uint32_t a;
    asm("{ .reg .u64 t; cvta.to.shared.u64 t, %1; cvt.u32.u64 %0, t; }" : "=r"(a) : "l"(p));
    return a;
}
#define CP16(dst, src) asm volatile("cp.async.cg.shared.global [%0], [%1], 16;" :: "r"(dst), "l"(src))
#define CP_COMMIT()    asm volatile("cp.async.commit_group;" ::: "memory")
#define CP_WAIT0()     asm volatile("cp.async.wait_group 0;" ::: "memory")
#define CP_WAIT1()     asm volatile("cp.async.wait_group 1;" ::: "memory")

// =====================================================================
// Prep: interleave + tf32-round x and W.
// x[m][k]  -> g_xi[(((m>>4)*128 + (k>>3))*32 + (m&7)*4 + (k&3))*4 + ((m>>3)&1) + 2*((k>>2)&1)]
// W[n][k]  -> g_wi[t][(((k>>4)*128 + (n>>3))*32 + (n&7)*4 + (k&3))*4 + ((k>>2)&3)]
// =====================================================================
__global__ __launch_bounds__(256)
void prep_kernel(const float* __restrict__ x, const float* __restrict__ Wk,
                 const float* __restrict__ Wv, const float* __restrict__ Wq)
{
    const int gi = blockIdx.x * 256 + threadIdx.x;
    if (blockIdx.y == 0) {
        if (gi < 4096*1024/4) {
            int m = gi >> 8, j = gi & 255;           // k = 4j..4j+3
            float4 v = ((const float4*)x)[gi];
            rnd4(v);
            int g = m >> 4, gm = m & 15;
            int base = (((g * 128 + (j >> 1)) * 32 + (gm & 7) * 4) << 2)
                       + ((gm >> 3) & 1) + 2 * (j & 1);
            g_xi[base     ] = v.x;
            g_xi[base +  4] = v.y;
            g_xi[base +  8] = v.z;
            g_xi[base + 12] = v.w;
        }
    } else {
        if (gi < 1024*1024/4) {
            const float* W = (blockIdx.y == 1) ? Wk : (blockIdx.y == 2) ? Wv : Wq;
            float* dst = g_wi[blockIdx.y - 1];
            int n = gi >> 8, j = gi & 255;           // k = 4j..4j+3
            float4 v = ((const float4*)W)[gi];
            rnd4(v);
            int base = ((((j >> 2) * 128 + (n >> 3)) * 32 + (n & 7) * 4) << 2) + (j & 3);
            dst[base     ] = v.x;
            dst[base +  4] = v.y;
            dst[base +  8] = v.z;
            dst[base + 12] = v.w;
        }
    }
}

// =====================================================================
// Merged projection: C[m,n] = sum_e x[m,e]*W[n,e], N-dim = 3 weights x 1024.
// CTA 128x128, 8 warps (4x2), warp 32x64, BK=32, cp.async double-buffered.
// smem floats: A[2] @ 0/4096 ; W[2] @ 8192/12288   (64KB)
// mode (= blockIdx.x>>3): 0 K-interleave, 1 V-interleave, 2 Q natural+cos.
// =====================================================================
#define PJ_SMEM (16384*4)

__global__ __launch_bounds__(256, 2)
void proj_mma(const float* __restrict__ theta)
{
    extern __shared__ float sm[];
    const uint32_t sb = smem_u32(sm);
    const int tid = threadIdx.x;
    const int wid = tid >> 5, lane = tid & 31;
    const int gid = lane >> 2, tig = lane & 3;
    const int wm = wid >> 1, wn = wid & 1;
    const int row0 = blockIdx.y * 128;
    const int col0g = blockIdx.x * 128;
    const int mode = col0g >> 10;
    const int coll = col0g & 1023;
    const float* Wint = g_wi[mode];

    float acc[2][8][4];
    #pragma unroll
    for (int i = 0; i < 2; i++)
        #pragma unroll
        for (int j = 0; j < 8; j++)
            #pragma unroll
            for (int e = 0; e < 4; e++) acc[i][j][e] = 0.f;

    const float* Ab = g_xi + (size_t)(row0 >> 4) * 128 * 128;  // base of m-groups
    const float* Wb = Wint + (size_t)(coll >> 3) * 128;        // ng base within kg row

    auto issue = [&](int ch, int b) {
        uint32_t adst = sb + (b * 4096) * 4;
        uint32_t wdst = sb + (8192 + b * 4096) * 4;
        #pragma unroll
        for (int i = 0; i < 4; i++) {                 // A: 1024 x 16B
            int c = tid + i * 256;
            int g_l = c >> 7, rem = c & 127, ks_l = rem >> 5, ln = rem & 31;
            CP16(adst + ((g_l * 4 + ks_l) * 128 + ln * 4) * 4,
                 Ab + ((size_t)g_l * 128 + ch * 4 + ks_l) * 128 + ln * 4);
        }
        #pragma unroll
        for (int i = 0; i < 4; i++) {                 // W: 1024 x 16B
            int c = tid + i * 256;
            int kg_l = c >> 9, rem = c & 511, ng_l = rem >> 5, ln = rem & 31;
            CP16(wdst + ((kg_l * 16 + ng_l) * 128 + ln * 4) * 4,
                 Wb + ((size_t)(ch * 2 + kg_l) * 128 + ng_l) * 128 + ln * 4);
        }
        CP_COMMIT();
    };

    issue(0, 0);
    #pragma unroll 1
    for (int ch = 0; ch < 32; ch++) {
        const int buf = ch & 1;
        if (ch < 31) issue(ch + 1, buf ^ 1);
        if (ch < 31) { CP_WAIT1(); } else { CP_WAIT0(); }
        __syncthreads();

        const float* As = sm + buf * 4096;
        const float* Ws = sm + 8192 + buf * 4096;
        #pragma unroll
        for (int qg = 0; qg < 2; qg++) {
            float4 af[2][2];
            #pragma unroll
            for (int tm = 0; tm < 2; tm++)
                #pragma unroll
                for (int kso = 0; kso < 2; kso++)
                    af[tm][kso] = *(const float4*)(As + ((wm*2+tm)*4 + qg*2+kso) * 128 + lane * 4);
            #pragma unroll
            for (int tn = 0; tn < 8; tn++) {
                float4 wb = *(const float4*)(Ws + (qg*16 + wn*8 + tn) * 128 + lane * 4);
                #pragma unroll
                for (int tm = 0; tm < 2; tm++) {
                    mma8f(acc[tm][tn], af[tm][0], wb.x, wb.y);
                    mma8f(acc[tm][tn], af[tm][1], wb.z, wb.w);
                }
            }
        }
        __syncthreads();
    }

    // epilogue scatter (tf32-rounded)
    #pragma unroll
    for (int tm = 0; tm < 2; tm++) {
        #pragma unroll
        for (int tn = 0; tn < 8; tn++) {
            #pragma unroll
            for (int e = 0; e < 4; e++) {
                int m = row0 + wm * 32 + tm * 16 + gid + (e >= 2 ? 8 : 0);
                int nn = coll + wn * 64 + tn * 8 + 2 * tig + (e & 1);
                int b = m >> 11, s = m & (SSEQ - 1);
                int h = nn >> 6, d = nn & (DKK - 1);
                int bh = b * HHEADS + h;
                float v = acc[tm][tn][e];
                size_t idx;
                if (mode == 0) {
                    int tile = s >> 6, ks = s & 63;
                    int tnk = ks >> 3, gidk = ks & 7;
                    int qg = d >> 4, dk = d & 15;
                    idx = (size_t)bh * 131072 + tile * 4096
                        + (((qg * 8 + tnk) * 32 + gidk * 4 + (dk & 3)) << 2) + (dk >> 2);
                } else if (mode == 1) {
                    int tile = s >> 6, ks = s & 63;
                    int j = ks >> 3, kk = ks & 7;
                    int dn = d >> 3, gidd = d & 7;
                    idx = (size_t)bh * 131072 + tile * 4096
                        + (((j * 4 + (dn >> 1)) * 32 + gidd * 4 + (kk & 3)) << 2)
                        + ((dn & 1) * 2 + (kk >> 2));
                } else {
                    v = cosf(v + __ldg(&theta[d])) * 0.125f;
                    idx = ((size_t)bh * SSEQ + s) * DKK + d;
                }
                float* dst = (mode == 0) ? g_k : (mode == 1) ? g_v : g_q;
                dst[idx] = to_tf32(v);
            }
        }
    }
}

// =====================================================================
// Attention: CTA = 128q x 1 head, 8 warps, warp = 16q x 64keys x 64d.
// Q frags in regs; K,V pre-interleaved so every frag = conflict-free LDS.128.
// P via quad-shuffle transpose (no smem). Exact softmax, no max subtraction.
// smem floats: K[2] @ 0/4096 ; V[2] @ 8192/12288   (64KB)
// =====================================================================
#define AT_SMEM (16384*4)

__global__ __launch_bounds__(256, 2)
void attn_mma(float* __restrict__ out)
{
    extern __shared__ float sm[];
    const uint32_t sb = smem_u32(sm);
    const int tid = threadIdx.x;
    const int wid = tid >> 5, lane = tid & 31;
    const int gid = lane >> 2, tig = lane & 3;
    const int bh = blockIdx.y;
    const int s0 = blockIdx.x * 128;

    // ---- Q fragments in registers (once) ----
    float4 qf[8];
    {
        const float* qb = g_q + ((size_t)bh * SSEQ + s0 + wid * 16) * DKK;
        #pragma unroll
        for (int m = 0; m < 8; m++) {
            int c = 8 * m + tig;
            qf[m] = make_float4(qb[gid * DKK + c],     qb[(gid + 8) * DKK + c],
                                qb[gid * DKK + c + 4], qb[(gid + 8) * DKK + c + 4]);
        }
    }

    const float* kg = g_k + (size_t)bh * 131072;
    const float* vg = g_v + (size_t)bh * 131072;

    auto issue = [&](int t, int b) {
        uint32_t kdst = sb + (b * 4096) * 4;
        uint32_t vdst = sb + (8192 + b * 4096) * 4;
        const float* ks = kg + (size_t)t * 4096;
        const float* vs = vg + (size_t)t * 4096;
        #pragma unroll
        for (int i = 0; i < 4; i++) {
            int c = tid + i * 256;
            CP16(kdst + c * 16, ks + c * 4);
        }
        #pragma unroll
        for (int i = 0; i < 4; i++) {
            int c = tid + i * 256;
            CP16(vdst + c * 16, vs + c * 4);
        }
        CP_COMMIT();
    };

    float oacc[8][4];
    #pragma unroll
    for (int dn = 0; dn < 8; dn++)
        #pragma unroll
        for (int e = 0; e < 4; e++) oacc[dn][e] = 0.f;
    float lsum0 = 0.f, lsum1 = 0.f;

    const int srcA = (lane & ~3) | (tig >> 1);
    const int srcB = srcA + 2;
    const bool odd = (tig & 1);

    issue(0, 0);
    #pragma unroll 1
    for (int t = 0; t < 32; t++) {
        const int buf = t & 1;
        if (t < 31) issue(t + 1, buf ^ 1);
        if (t < 31) { CP_WAIT1(); } else { CP_WAIT0(); }
        __syncthreads();

        const float* Kp = sm + buf * 4096;
        const float* Vp = sm + 8192 + buf * 4096;

        // ---- S = Q @ K^T ----
        float sacc[8][4];
        #pragma unroll
        for (int tn = 0; tn < 8; tn++)
            #pragma unroll
            for (int e = 0; e < 4; e++) sacc[tn][e] = 0.f;

        #pragma unroll
        for (int qg = 0; qg < 4; qg++) {
            #pragma unroll
            for (int tn = 0; tn < 8; tn++) {
                float4 kb = *(const float4*)(Kp + (qg * 8 + tn) * 128 + lane * 4);
                mma8f(sacc[tn], qf[2 * qg    ], kb.x, kb.y);
                mma8f(sacc[tn], qf[2 * qg + 1], kb.z, kb.w);
            }
        }

        // ---- P = exp(S), row sums ----
        #pragma unroll
        for (int tn = 0; tn < 8; tn++) {
            float p0 = to_tf32(__expf(sacc[tn][0]));
            float p1 = to_tf32(__expf(sacc[tn][1]));
            float p2 = to_tf32(__expf(sacc[tn][2]));
            float p3 = to_tf32(__expf(sacc[tn][3]));
            lsum0 += p0 + p1; lsum1 += p2 + p3;
            sacc[tn][0] = p0; sacc[tn][1] = p1; sacc[tn][2] = p2; sacc[tn][3] = p3;
        }

        // ---- O += P @ V  (P via quad shuffles; V frags = LDS.128) ----
        #pragma unroll
        for (int j = 0; j < 8; j++) {
            const float* p = sacc[j];
            float v00 = __shfl_sync(0xffffffffu, p[0], srcA);
            float v01 = __shfl_sync(0xffffffffu, p[1], srcA);
            float v10 = __shfl_sync(0xffffffffu, p[2], srcA);
            float v11 = __shfl_sync(0xffffffffu, p[3], srcA);
            float v20 = __shfl_sync(0xffffffffu, p[0], srcB);
            float v21 = __shfl_sync(0xffffffffu, p[1], srcB);
            float v30 = __shfl_sync(0xffffffffu, p[2], srcB);
            float v31 = __shfl_sync(0xffffffffu, p[3], srcB);
            float4 aA;
            aA.x = odd ? v01 : v00; aA.y = odd ? v11 : v10;
            aA.z = odd ? v21 : v20; aA.w = odd ? v31 : v30;

            #pragma unroll
            for (int dnp = 0; dnp < 4; dnp++) {
                float4 vb = *(const float4*)(Vp + (j * 4 + dnp) * 128 + lane * 4);
                mma8f(oacc[2 * dnp    ], aA, vb.x, vb.y);
                mma8f(oacc[2 * dnp + 1], aA, vb.z, vb.w);
            }
        }
        __syncthreads();
    }

    // ---- finalize l and write out ----
    lsum0 += __shfl_xor_sync(0xffffffffu, lsum0, 1);
    lsum0 += __shfl_xor_sync(0xffffffffu, lsum0, 2);
    lsum1 += __shfl_xor_sync(0xffffffffu, lsum1, 1);
    lsum1 += __shfl_xor_sync(0xffffffffu, lsum1, 2);
    const float inv0 = 1.f / lsum0;
    const float inv1 = 1.f / lsum1;

    const int b = bh >> 4, h = bh & (HHEADS - 1);
    float* o0 = out + ((size_t)b * SSEQ + s0 + wid * 16 + gid) * EEMB + h * DKK;
    float* o1 = o0 + 8 * EEMB;
    #pragma unroll
    for (int dn = 0; dn < 8; dn++) {
        int c = dn * 8 + 2 * tig;
        *(float2*)(o0 + c) = make_float2(oacc[dn][0] * inv0, oacc[dn][1] * inv0);
        *(float2*)(o1 + c) = make_float2(oacc[dn][2] * inv1, oacc[dn][3] * inv1);
    }
}

// ===================== launch =====================
extern "C" void kernel_launch(void* const* d_in, const int* in_sizes, int n_in,
                              void* d_out, int out_size)
{
    const float* x     = (const float*)d_in[0];
    const float* Wk    = (const float*)d_in[1];
    const float* Wv    = (const float*)d_in[2];
    const float* Wq    = (const float*)d_in[3];
    const float* theta = (const float*)d_in[4];
    float* out = (float*)d_out;

    cudaFuncSetAttribute(proj_mma, cudaFuncAttributeMaxDynamicSharedMemorySize, PJ_SMEM);
    cudaFuncSetAttribute(attn_mma, cudaFuncAttributeMaxDynamicSharedMemorySize, AT_SMEM);

    prep_kernel<<<dim3(4096, 4), 256>>>(x, Wk, Wv, Wq);

    dim3 gp(3 * EEMB / 128, (BBATCH * SSEQ) / 128);   // (24, 32)
    proj_mma<<<gp, 256, PJ_SMEM>>>(theta);

    dim3 ga(SSEQ / 128, BBATCH * HHEADS);              // (16, 32)
    attn_mma<<<ga, 256, AT_SMEM>>>(out);
}

// round 7
// speedup vs baseline: 2.0532x; 1.1015x over previous
#include <cuda_runtime.h>
#include <math.h>
#include <stdint.h>

#define BBATCH 2
#define SSEQ 2048
#define EEMB 1024
#define HHEADS 16
#define DKK 64
#define BHS (BBATCH*HHEADS*SSEQ)

// Scratch
__device__ float g_xi[4096*1024];      // x: a-frag interleave [m>>4][k>>3][lane32][comp4]
__device__ float g_wi[3][1024*1024];   // W: b-frag interleave [k>>4][n>>3][lane32][comp4]
__device__ float g_k[BHS*DKK];         // K: [bh][tile][qg4][key>>3][lane32][comp4], keys PERMUTED in 8-groups
__device__ float g_v[BHS*DKK];         // V: [bh][tile][j8][dnp4][lane32][comp4]
__device__ float g_q[BHS*DKK];         // Q: natural [bh][s][d]

// ---------------- helpers ----------------
__device__ __forceinline__ float to_tf32(float x){
    float r; asm("cvt.rna.tf32.f32 %0, %1;" : "=f"(r) : "f"(x)); return r;
}
__device__ __forceinline__ void rnd4(float4& v){
    v.x = to_tf32(v.x); v.y = to_tf32(v.y); v.z = to_tf32(v.z); v.w = to_tf32(v.w);
}
__device__ __forceinline__ void mma8(float* d,
                                     uint32_t a0, uint32_t a1, uint32_t a2, uint32_t a3,
                                     uint32_t b0, uint32_t b1)
{
    asm volatile("mma.sync.aligned.m16n8k8.row.col.f32.tf32.tf32.f32 "
        "{%0,%1,%2,%3}, {%4,%5,%6,%7}, {%8,%9}, {%0,%1,%2,%3};"
        : "+f"(d[0]), "+f"(d[1]), "+f"(d[2]), "+f"(d[3])
        : "r"(a0), "r"(a1), "r"(a2), "r"(a3), "r"(b0), "r"(b1));
}
#define U(x) __float_as_uint(x)
__device__ __forceinline__ void mma8f(float* d, const float4& a, float b0, float b1){
    mma8(d, U(a.x), U(a.y), U(a.z), U(a.w), U(b0), U(b1));
}
__device__ __forceinline__ void mma8e(float* d, float e0, float e1, float e2, float e3,
                                      float b0, float b1){
    mma8(d, U(e0), U(e1), U(e2), U(e3), U(b0), U(b1));
}
__device__ __forceinline__ uint32_t smem_u32(const void* p){
    uint32_t a;
    asm("{ .reg .u64 t; cvta.to.shared.u64 t, %1; cvt.u32.u64 %0, t; }" : "=r"(a) : "l"(p));
    return a;
}
#define CP16(dst, src) asm volatile("cp.async.cg.shared.global [%0], [%1], 16;" :: "r"(dst), "l"(src))
#define CP_COMMIT()    asm volatile("cp.async.commit_group;" ::: "memory")
#define CP_WAIT0()     asm volatile("cp.async.wait_group 0;" ::: "memory")
#define CP_WAIT1()     asm volatile("cp.async.wait_group 1;" ::: "memory")

// =====================================================================
// Prep: interleave + tf32-round x and W.
// =====================================================================
__global__ __launch_bounds__(256)
void prep_kernel(const float* __restrict__ x, const float* __restrict__ Wk,
                 const float* __restrict__ Wv, const float* __restrict__ Wq)
{
    const int gi = blockIdx.x * 256 + threadIdx.x;
    if (blockIdx.y == 0) {
        if (gi < 4096*1024/4) {
            int m = gi >> 8, j = gi & 255;           // k = 4j..4j+3
            float4 v = ((const float4*)x)[gi];
            rnd4(v);
            int g = m >> 4, gm = m & 15;
            int base = (((g * 128 + (j >> 1)) * 32 + (gm & 7) * 4) << 2)
                       + ((gm >> 3) & 1) + 2 * (j & 1);
            g_xi[base     ] = v.x;
            g_xi[base +  4] = v.y;
            g_xi[base +  8] = v.z;
            g_xi[base + 12] = v.w;
        }
    } else {
        if (gi < 1024*1024/4) {
            const float* W = (blockIdx.y == 1) ? Wk : (blockIdx.y == 2) ? Wv : Wq;
            float* dst = g_wi[blockIdx.y - 1];
            int n = gi >> 8, j = gi & 255;
            float4 v = ((const float4*)W)[gi];
            rnd4(v);
            int base = ((((j >> 2) * 128 + (n >> 3)) * 32 + (n & 7) * 4) << 2) + (j & 3);
            dst[base     ] = v.x;
            dst[base +  4] = v.y;
            dst[base +  8] = v.z;
            dst[base + 12] = v.w;
        }
    }
}

// =====================================================================
// Merged projection (unchanged except K key-permutation in epilogue).
// =====================================================================
#define PJ_SMEM (16384*4)

__global__ __launch_bounds__(256, 2)
void proj_mma(const float* __restrict__ theta)
{
    extern __shared__ float sm[];
    const uint32_t sb = smem_u32(sm);
    const int tid = threadIdx.x;
    const int wid = tid >> 5, lane = tid & 31;
    const int gid = lane >> 2, tig = lane & 3;
    const int wm = wid >> 1, wn = wid & 1;
    const int row0 = blockIdx.y * 128;
    const int col0g = blockIdx.x * 128;
    const int mode = col0g >> 10;
    const int coll = col0g & 1023;
    const float* Wint = g_wi[mode];

    float acc[2][8][4];
    #pragma unroll
    for (int i = 0; i < 2; i++)
        #pragma unroll
        for (int j = 0; j < 8; j++)
            #pragma unroll
            for (int e = 0; e < 4; e++) acc[i][j][e] = 0.f;

    const float* Ab = g_xi + (size_t)(row0 >> 4) * 128 * 128;
    const float* Wb = Wint + (size_t)(coll >> 3) * 128;

    auto issue = [&](int ch, int b) {
        uint32_t adst = sb + (b * 4096) * 4;
        uint32_t wdst = sb + (8192 + b * 4096) * 4;
        #pragma unroll
        for (int i = 0; i < 4; i++) {
            int c = tid + i * 256;
            int g_l = c >> 7, rem = c & 127, ks_l = rem >> 5, ln = rem & 31;
            CP16(adst + ((g_l * 4 + ks_l) * 128 + ln * 4) * 4,
                 Ab + ((size_t)g_l * 128 + ch * 4 + ks_l) * 128 + ln * 4);
        }
        #pragma unroll
        for (int i = 0; i < 4; i++) {
            int c = tid + i * 256;
            int kg_l = c >> 9, rem = c & 511, ng_l = rem >> 5, ln = rem & 31;
            CP16(wdst + ((kg_l * 16 + ng_l) * 128 + ln * 4) * 4,
                 Wb + ((size_t)(ch * 2 + kg_l) * 128 + ng_l) * 128 + ln * 4);
        }
        CP_COMMIT();
    };

    issue(0, 0);
    #pragma unroll 1
    for (int ch = 0; ch < 32; ch++) {
        const int buf = ch & 1;
        if (ch < 31) issue(ch + 1, buf ^ 1);
        if (ch < 31) { CP_WAIT1(); } else { CP_WAIT0(); }
        __syncthreads();

        const float* As = sm + buf * 4096;
        const float* Ws = sm + 8192 + buf * 4096;
        #pragma unroll
        for (int qg = 0; qg < 2; qg++) {
            float4 af[2][2];
            #pragma unroll
            for (int tm = 0; tm < 2; tm++)
                #pragma unroll
                for (int kso = 0; kso < 2; kso++)
                    af[tm][kso] = *(const float4*)(As + ((wm*2+tm)*4 + qg*2+kso) * 128 + lane * 4);
            #pragma unroll
            for (int tn = 0; tn < 8; tn++) {
                float4 wb = *(const float4*)(Ws + (qg*16 + wn*8 + tn) * 128 + lane * 4);
                #pragma unroll
                for (int tm = 0; tm < 2; tm++) {
                    mma8f(acc[tm][tn], af[tm][0], wb.x, wb.y);
                    mma8f(acc[tm][tn], af[tm][1], wb.z, wb.w);
                }
            }
        }
        __syncthreads();
    }

    // epilogue scatter (tf32-rounded). K gets key-permuted columns.
    #pragma unroll
    for (int tm = 0; tm < 2; tm++) {
        #pragma unroll
        for (int tn = 0; tn < 8; tn++) {
            #pragma unroll
            for (int e = 0; e < 4; e++) {
                int m = row0 + wm * 32 + tm * 16 + gid + (e >= 2 ? 8 : 0);
                int nn = coll + wn * 64 + tn * 8 + 2 * tig + (e & 1);
                int b = m >> 11, s = m & (SSEQ - 1);
                int h = nn >> 6, d = nn & (DKK - 1);
                int bh = b * HHEADS + h;
                float v = acc[tm][tn][e];
                size_t idx;
                if (mode == 0) {
                    int tile = s >> 6, ks = s & 63;
                    int tnk = ks >> 3, kk = ks & 7;
                    int col = ((kk & 3) << 1) | (kk >> 2);   // key permutation
                    int qg = d >> 4, dk = d & 15;
                    idx = (size_t)bh * 131072 + tile * 4096
                        + (((qg * 8 + tnk) * 32 + col * 4 + (dk & 3)) << 2) + (dk >> 2);
                } else if (mode == 1) {
                    int tile = s >> 6, ks = s & 63;
                    int j = ks >> 3, kk = ks & 7;
                    int dn = d >> 3, gidd = d & 7;
                    idx = (size_t)bh * 131072 + tile * 4096
                        + (((j * 4 + (dn >> 1)) * 32 + gidd * 4 + (kk & 3)) << 2)
                        + ((dn & 1) * 2 + (kk >> 2));
                } else {
                    v = cosf(v + __ldg(&theta[d])) * 0.125f;
                    idx = ((size_t)bh * SSEQ + s) * DKK + d;
                }
                float* dst = (mode == 0) ? g_k : (mode == 1) ? g_v : g_q;
                dst[idx] = to_tf32(v);
            }
        }
    }
}

// =====================================================================
// Attention: CTA = 256q x 1 head, 8 warps, warp = 32q x 64keys x 64d.
// Key-permuted K layout -> S accumulator IS the PV A-operand (no shuffles).
// Q frags in regs. K/V smem frags = conflict-free LDS.128. Exact softmax.
// smem floats: K[2] @ 0/4096 ; V[2] @ 8192/12288   (64KB)
// =====================================================================
#define AT_SMEM (16384*4)

__global__ __launch_bounds__(256, 1)
void attn_mma(float* __restrict__ out)
{
    extern __shared__ float sm[];
    const uint32_t sb = smem_u32(sm);
    const int tid = threadIdx.x;
    const int wid = tid >> 5, lane = tid & 31;
    const int gid = lane >> 2, tig = lane & 3;
    const int bh = blockIdx.y;
    const int s0 = blockIdx.x * 256;

    // ---- Q fragments in registers: 2 m-groups x 8 k-steps ----
    float4 qf[2][8];
    #pragma unroll
    for (int mg = 0; mg < 2; mg++) {
        const float* qb = g_q + ((size_t)bh * SSEQ + s0 + wid * 32 + mg * 16) * DKK;
        #pragma unroll
        for (int ks = 0; ks < 8; ks++) {
            int c = 8 * ks + tig;
            qf[mg][ks] = make_float4(qb[gid * DKK + c],     qb[(gid + 8) * DKK + c],
                                     qb[gid * DKK + c + 4], qb[(gid + 8) * DKK + c + 4]);
        }
    }

    const float* kg = g_k + (size_t)bh * 131072;
    const float* vg = g_v + (size_t)bh * 131072;

    auto issue = [&](int t, int b) {
        uint32_t kdst = sb + (b * 4096) * 4;
        uint32_t vdst = sb + (8192 + b * 4096) * 4;
        const float* ks = kg + (size_t)t * 4096;
        const float* vs = vg + (size_t)t * 4096;
        #pragma unroll
        for (int i = 0; i < 4; i++) {
            int c = tid + i * 256;
            CP16(kdst + c * 16, ks + c * 4);
        }
        #pragma unroll
        for (int i = 0; i < 4; i++) {
            int c = tid + i * 256;
            CP16(vdst + c * 16, vs + c * 4);
        }
        CP_COMMIT();
    };

    float oacc[2][8][4];
    #pragma unroll
    for (int mg = 0; mg < 2; mg++)
        #pragma unroll
        for (int dn = 0; dn < 8; dn++)
            #pragma unroll
            for (int e = 0; e < 4; e++) oacc[mg][dn][e] = 0.f;
    float lsum[2][2] = {{0.f, 0.f}, {0.f, 0.f}};

    issue(0, 0);
    #pragma unroll 1
    for (int t = 0; t < 32; t++) {
        const int buf = t & 1;
        if (t < 31) issue(t + 1, buf ^ 1);
        if (t < 31) { CP_WAIT1(); } else { CP_WAIT0(); }
        __syncthreads();

        const float* Kp = sm + buf * 4096;
        const float* Vp = sm + 8192 + buf * 4096;

        // ---- S = Q @ K^T (key-permuted columns) ----
        float sacc[2][8][4];
        #pragma unroll
        for (int mg = 0; mg < 2; mg++)
            #pragma unroll
            for (int tn = 0; tn < 8; tn++)
                #pragma unroll
                for (int e = 0; e < 4; e++) sacc[mg][tn][e] = 0.f;

        #pragma unroll
        for (int qg = 0; qg < 4; qg++) {
            #pragma unroll
            for (int tn = 0; tn < 8; tn++) {
                float4 kb = *(const float4*)(Kp + (qg * 8 + tn) * 128 + lane * 4);
                #pragma unroll
                for (int mg = 0; mg < 2; mg++) {
                    mma8f(sacc[mg][tn], qf[mg][2 * qg    ], kb.x, kb.y);
                    mma8f(sacc[mg][tn], qf[mg][2 * qg + 1], kb.z, kb.w);
                }
            }
        }

        // ---- P = exp(S), row sums (e0,e1 row gid ; e2,e3 row gid+8) ----
        #pragma unroll
        for (int mg = 0; mg < 2; mg++)
            #pragma unroll
            for (int tn = 0; tn < 8; tn++) {
                float p0 = to_tf32(__expf(sacc[mg][tn][0]));
                float p1 = to_tf32(__expf(sacc[mg][tn][1]));
                float p2 = to_tf32(__expf(sacc[mg][tn][2]));
                float p3 = to_tf32(__expf(sacc[mg][tn][3]));
                lsum[mg][0] += p0 + p1;
                lsum[mg][1] += p2 + p3;
                sacc[mg][tn][0] = p0; sacc[mg][tn][1] = p1;
                sacc[mg][tn][2] = p2; sacc[mg][tn][3] = p3;
            }

        // ---- O += P @ V : A-frag = (e0, e2, e1, e3), no shuffles ----
        #pragma unroll
        for (int j = 0; j < 8; j++) {
            #pragma unroll
            for (int dnp = 0; dnp < 4; dnp++) {
                float4 vb = *(const float4*)(Vp + (j * 4 + dnp) * 128 + lane * 4);
                #pragma unroll
                for (int mg = 0; mg < 2; mg++) {
                    const float* p = sacc[mg][j];
                    mma8e(oacc[mg][2 * dnp    ], p[0], p[2], p[1], p[3], vb.x, vb.y);
                    mma8e(oacc[mg][2 * dnp + 1], p[0], p[2], p[1], p[3], vb.z, vb.w);
                }
            }
        }
        __syncthreads();
    }

    // ---- finalize l (quad reduce) and write out ----
    #pragma unroll
    for (int mg = 0; mg < 2; mg++)
        #pragma unroll
        for (int r = 0; r < 2; r++) {
            lsum[mg][r] += __shfl_xor_sync(0xffffffffu, lsum[mg][r], 1);
            lsum[mg][r] += __shfl_xor_sync(0xffffffffu, lsum[mg][r], 2);
        }

    const int b = bh >> 4, h = bh & (HHEADS - 1);
    #pragma unroll
    for (int mg = 0; mg < 2; mg++) {
        const float inv0 = 1.f / lsum[mg][0];
        const float inv1 = 1.f / lsum[mg][1];
        float* o0 = out + ((size_t)b * SSEQ + s0 + wid * 32 + mg * 16 + gid) * EEMB + h * DKK;
        float* o1 = o0 + 8 * EEMB;
        #pragma unroll
        for (int dn = 0; dn < 8; dn++) {
            int c = dn * 8 + 2 * tig;
            *(float2*)(o0 + c) = make_float2(oacc[mg][dn][0] * inv0, oacc[mg][dn][1] * inv0);
            *(float2*)(o1 + c) = make_float2(oacc[mg][dn][2] * inv1, oacc[mg][dn][3] * inv1);
        }
    }
}

// ===================== launch =====================
extern "C" void kernel_launch(void* const* d_in, const int* in_sizes, int n_in,
                              void* d_out, int out_size)
{
    const float* x     = (const float*)d_in[0];
    const float* Wk    = (const float*)d_in[1];
    const float* Wv    = (const float*)d_in[2];
    const float* Wq    = (const float*)d_in[3];
    const float* theta = (const float*)d_in[4];
    float* out = (float*)d_out;

    cudaFuncSetAttribute(proj_mma, cudaFuncAttributeMaxDynamicSharedMemorySize, PJ_SMEM);
    cudaFuncSetAttribute(attn_mma, cudaFuncAttributeMaxDynamicSharedMemorySize, AT_SMEM);

    prep_kernel<<<dim3(4096, 4), 256>>>(x, Wk, Wv, Wq);

    dim3 gp(3 * EEMB / 128, (BBATCH * SSEQ) / 128);   // (24, 32)
    proj_mma<<<gp, 256, PJ_SMEM>>>(theta);

    dim3 ga(SSEQ / 256, BBATCH * HHEADS);              // (8, 32)
    attn_mma<<<ga, 256, AT_SMEM>>>(out);
}

// round 8
// speedup vs baseline: 2.0569x; 1.0018x over previous
#include <cuda_runtime.h>
#include <math.h>
#include <stdint.h>

#define BBATCH 2
#define SSEQ 2048
#define EEMB 1024
#define HHEADS 16
#define DKK 64
#define BHS (BBATCH*HHEADS*SSEQ)

// Scratch
__device__ float g_xi[4096*1024];      // x: a-frag interleave [m>>4][k>>3][lane32][comp4]
__device__ float g_wi[3][1024*1024];   // W: b-frag interleave [k>>4][n>>3][lane32][comp4]
__device__ float g_k[BHS*DKK];         // K: [bh][tile][qg4][key>>3][lane32][comp4], keys PERMUTED in 8-groups
__device__ float g_v[BHS*DKK];         // V: [bh][tile][j8][dnp4][lane32][comp4]
__device__ float g_q[BHS*DKK];         // Q: natural [bh][s][d]

// ---------------- helpers ----------------
__device__ __forceinline__ float to_tf32(float x){
    float r; asm("cvt.rna.tf32.f32 %0, %1;" : "=f"(r) : "f"(x)); return r;
}
__device__ __forceinline__ void rnd4(float4& v){
    v.x = to_tf32(v.x); v.y = to_tf32(v.y); v.z = to_tf32(v.z); v.w = to_tf32(v.w);
}
__device__ __forceinline__ void mma8(float* d,
                                     uint32_t a0, uint32_t a1, uint32_t a2, uint32_t a3,
                                     uint32_t b0, uint32_t b1)
{
    asm volatile("mma.sync.aligned.m16n8k8.row.col.f32.tf32.tf32.f32 "
        "{%0,%1,%2,%3}, {%4,%5,%6,%7}, {%8,%9}, {%0,%1,%2,%3};"
        : "+f"(d[0]), "+f"(d[1]), "+f"(d[2]), "+f"(d[3])
        : "r"(a0), "r"(a1), "r"(a2), "r"(a3), "r"(b0), "r"(b1));
}
#define U(x) __float_as_uint(x)
__device__ __forceinline__ void mma8f(float* d, const float4& a, float b0, float b1){
    mma8(d, U(a.x), U(a.y), U(a.z), U(a.w), U(b0), U(b1));
}
__device__ __forceinline__ void mma8e(float* d, float e0, float e1, float e2, float e3,
                                      float b0, float b1){
    mma8(d, U(e0), U(e1), U(e2), U(e3), U(b0), U(b1));
}
__device__ __forceinline__ uint32_t smem_u32(const void* p){
    uint32_t a;
    asm("{ .reg .u64 t; cvta.to.shared.u64 t, %1; cvt.u32.u64 %0, t; }" : "=r"(a) : "l"(p));
    return a;
}
#define CP16(dst, src) asm volatile("cp.async.cg.shared.global [%0], [%1], 16;" :: "r"(dst), "l"(src))
#define CP_COMMIT()    asm volatile("cp.async.commit_group;" ::: "memory")
#define CP_WAIT0()     asm volatile("cp.async.wait_group 0;" ::: "memory")
#define CP_WAIT1()     asm volatile("cp.async.wait_group 1;" ::: "memory")

// =====================================================================
// Prep: interleave + tf32-round x and W.
// =====================================================================
__global__ __launch_bounds__(256)
void prep_kernel(const float* __restrict__ x, const float* __restrict__ Wk,
                 const float* __restrict__ Wv, const float* __restrict__ Wq)
{
    const int gi = blockIdx.x * 256 + threadIdx.x;
    if (blockIdx.y == 0) {
        if (gi < 4096*1024/4) {
            int m = gi >> 8, j = gi & 255;           // k = 4j..4j+3
            float4 v = ((const float4*)x)[gi];
            rnd4(v);
            int g = m >> 4, gm = m & 15;
            int base = (((g * 128 + (j >> 1)) * 32 + (gm & 7) * 4) << 2)
                       + ((gm >> 3) & 1) + 2 * (j & 1);
            g_xi[base     ] = v.x;
            g_xi[base +  4] = v.y;
            g_xi[base +  8] = v.z;
            g_xi[base + 12] = v.w;
        }
    } else {
        if (gi < 1024*1024/4) {
            const float* W = (blockIdx.y == 1) ? Wk : (blockIdx.y == 2) ? Wv : Wq;
            float* dst = g_wi[blockIdx.y - 1];
            int n = gi >> 8, j = gi & 255;
            float4 v = ((const float4*)W)[gi];
            rnd4(v);
            int base = ((((j >> 2) * 128 + (n >> 3)) * 32 + (n & 7) * 4) << 2) + (j & 3);
            dst[base     ] = v.x;
            dst[base +  4] = v.y;
            dst[base +  8] = v.z;
            dst[base + 12] = v.w;
        }
    }
}

// =====================================================================
// Merged projection, 3-stage cp.async pipeline, ONE sync per chunk.
// smem floats: A[s] @ s*4096 (s=0..2); W[s] @ 12288 + s*4096  (96KB)
// =====================================================================
#define PJ_SMEM (24576*4)

__global__ __launch_bounds__(256, 2)
void proj_mma(const float* __restrict__ theta)
{
    extern __shared__ float sm[];
    const uint32_t sb = smem_u32(sm);
    const int tid = threadIdx.x;
    const int wid = tid >> 5, lane = tid & 31;
    const int gid = lane >> 2, tig = lane & 3;
    const int wm = wid >> 1, wn = wid & 1;
    const int row0 = blockIdx.y * 128;
    const int col0g = blockIdx.x * 128;
    const int mode = col0g >> 10;
    const int coll = col0g & 1023;
    const float* Wint = g_wi[mode];

    float acc[2][8][4];
    #pragma unroll
    for (int i = 0; i < 2; i++)
        #pragma unroll
        for (int j = 0; j < 8; j++)
            #pragma unroll
            for (int e = 0; e < 4; e++) acc[i][j][e] = 0.f;

    const float* Ab = g_xi + (size_t)(row0 >> 4) * 128 * 128;
    const float* Wb = Wint + (size_t)(coll >> 3) * 128;

    auto issue = [&](int ch, int b) {
        uint32_t adst = sb + (b * 4096) * 4;
        uint32_t wdst = sb + (12288 + b * 4096) * 4;
        #pragma unroll
        for (int i = 0; i < 4; i++) {
            int c = tid + i * 256;
            int g_l = c >> 7, rem = c & 127, ks_l = rem >> 5, ln = rem & 31;
            CP16(adst + ((g_l * 4 + ks_l) * 128 + ln * 4) * 4,
                 Ab + ((size_t)g_l * 128 + ch * 4 + ks_l) * 128 + ln * 4);
        }
        #pragma unroll
        for (int i = 0; i < 4; i++) {
            int c = tid + i * 256;
            int kg_l = c >> 9, rem = c & 511, ng_l = rem >> 5, ln = rem & 31;
            CP16(wdst + ((kg_l * 16 + ng_l) * 128 + ln * 4) * 4,
                 Wb + ((size_t)(ch * 2 + kg_l) * 128 + ng_l) * 128 + ln * 4);
        }
        CP_COMMIT();
    };

    issue(0, 0);
    issue(1, 1);
    int buf = 0;
    #pragma unroll 1
    for (int ch = 0; ch < 32; ch++) {
        if (ch == 31) { CP_WAIT0(); } else { CP_WAIT1(); }
        __syncthreads();
        if (ch + 2 < 32) {
            int nb = buf + 2; if (nb >= 3) nb -= 3;
            issue(ch + 2, nb);
        }

        const float* As = sm + buf * 4096;
        const float* Ws = sm + 12288 + buf * 4096;
        #pragma unroll
        for (int qg = 0; qg < 2; qg++) {
            float4 af[2][2];
            #pragma unroll
            for (int tm = 0; tm < 2; tm++)
                #pragma unroll
                for (int kso = 0; kso < 2; kso++)
                    af[tm][kso] = *(const float4*)(As + ((wm*2+tm)*4 + qg*2+kso) * 128 + lane * 4);
            #pragma unroll
            for (int tn = 0; tn < 8; tn++) {
                float4 wb = *(const float4*)(Ws + (qg*16 + wn*8 + tn) * 128 + lane * 4);
                #pragma unroll
                for (int tm = 0; tm < 2; tm++) {
                    mma8f(acc[tm][tn], af[tm][0], wb.x, wb.y);
                    mma8f(acc[tm][tn], af[tm][1], wb.z, wb.w);
                }
            }
        }
        if (++buf == 3) buf = 0;
    }

    // epilogue scatter (tf32-rounded). K gets key-permuted columns.
    #pragma unroll
    for (int tm = 0; tm < 2; tm++) {
        #pragma unroll
        for (int tn = 0; tn < 8; tn++) {
            #pragma unroll
            for (int e = 0; e < 4; e++) {
                int m = row0 + wm * 32 + tm * 16 + gid + (e >= 2 ? 8 : 0);
                int nn = coll + wn * 64 + tn * 8 + 2 * tig + (e & 1);
                int b = m >> 11, s = m & (SSEQ - 1);
                int h = nn >> 6, d = nn & (DKK - 1);
                int bh = b * HHEADS + h;
                float v = acc[tm][tn][e];
                size_t idx;
                if (mode == 0) {
                    int tile = s >> 6, ks = s & 63;
                    int tnk = ks >> 3, kk = ks & 7;
                    int col = ((kk & 3) << 1) | (kk >> 2);   // key permutation
                    int qg = d >> 4, dk = d & 15;
                    idx = (size_t)bh * 131072 + tile * 4096
                        + (((qg * 8 + tnk) * 32 + col * 4 + (dk & 3)) << 2) + (dk >> 2);
                } else if (mode == 1) {
                    int tile = s >> 6, ks = s & 63;
                    int j = ks >> 3, kk = ks & 7;
                    int dn = d >> 3, gidd = d & 7;
                    idx = (size_t)bh * 131072 + tile * 4096
                        + (((j * 4 + (dn >> 1)) * 32 + gidd * 4 + (kk & 3)) << 2)
                        + ((dn & 1) * 2 + (kk >> 2));
                } else {
                    v = cosf(v + __ldg(&theta[d])) * 0.125f;
                    idx = ((size_t)bh * SSEQ + s) * DKK + d;
                }
                float* dst = (mode == 0) ? g_k : (mode == 1) ? g_v : g_q;
                dst[idx] = to_tf32(v);
            }
        }
    }
}

// =====================================================================
// Attention: CTA = 256q x 1 head, 8 warps, warp = 32q x 64keys x 64d.
// 3-stage cp.async pipeline, ONE sync per key-tile. No shuffles (key perm).
// smem floats: K[s] @ s*4096 ; V[s] @ 12288 + s*4096   (96KB)
// =====================================================================
#define AT_SMEM (24576*4)

__global__ __launch_bounds__(256, 1)
void attn_mma(float* __restrict__ out)
{
    extern __shared__ float sm[];
    const uint32_t sb = smem_u32(sm);
    const int tid = threadIdx.x;
    const int wid = tid >> 5, lane = tid & 31;
    const int gid = lane >> 2, tig = lane & 3;
    const int bh = blockIdx.y;
    const int s0 = blockIdx.x * 256;

    // ---- Q fragments in registers: 2 m-groups x 8 k-steps ----
    float4 qf[2][8];
    #pragma unroll
    for (int mg = 0; mg < 2; mg++) {
        const float* qb = g_q + ((size_t)bh * SSEQ + s0 + wid * 32 + mg * 16) * DKK;
        #pragma unroll
        for (int ks = 0; ks < 8; ks++) {
            int c = 8 * ks + tig;
            qf[mg][ks] = make_float4(qb[gid * DKK + c],     qb[(gid + 8) * DKK + c],
                                     qb[gid * DKK + c + 4], qb[(gid + 8) * DKK + c + 4]);
        }
    }

    const float* kg = g_k + (size_t)bh * 131072;
    const float* vg = g_v + (size_t)bh * 131072;

    auto issue = [&](int t, int b) {
        uint32_t kdst = sb + (b * 4096) * 4;
        uint32_t vdst = sb + (12288 + b * 4096) * 4;
        const float* ks = kg + (size_t)t * 4096;
        const float* vs = vg + (size_t)t * 4096;
        #pragma unroll
        for (int i = 0; i < 4; i++) {
            int c = tid + i * 256;
            CP16(kdst + c * 16, ks + c * 4);
        }
        #pragma unroll
        for (int i = 0; i < 4; i++) {
            int c = tid + i * 256;
            CP16(vdst + c * 16, vs + c * 4);
        }
        CP_COMMIT();
    };

    float oacc[2][8][4];
    #pragma unroll
    for (int mg = 0; mg < 2; mg++)
        #pragma unroll
        for (int dn = 0; dn < 8; dn++)
            #pragma unroll
            for (int e = 0; e < 4; e++) oacc[mg][dn][e] = 0.f;
    float lsum[2][2] = {{0.f, 0.f}, {0.f, 0.f}};

    issue(0, 0);
    issue(1, 1);
    int buf = 0;
    #pragma unroll 1
    for (int t = 0; t < 32; t++) {
        if (t == 31) { CP_WAIT0(); } else { CP_WAIT1(); }
        __syncthreads();
        if (t + 2 < 32) {
            int nb = buf + 2; if (nb >= 3) nb -= 3;
            issue(t + 2, nb);
        }

        const float* Kp = sm + buf * 4096;
        const float* Vp = sm + 12288 + buf * 4096;

        // ---- S = Q @ K^T (key-permuted columns) ----
        float sacc[2][8][4];
        #pragma unroll
        for (int mg = 0; mg < 2; mg++)
            #pragma unroll
            for (int tn = 0; tn < 8; tn++)
                #pragma unroll
                for (int e = 0; e < 4; e++) sacc[mg][tn][e] = 0.f;

        #pragma unroll
        for (int qg = 0; qg < 4; qg++) {
            #pragma unroll
            for (int tn = 0; tn < 8; tn++) {
                float4 kb = *(const float4*)(Kp + (qg * 8 + tn) * 128 + lane * 4);
                #pragma unroll
                for (int mg = 0; mg < 2; mg++) {
                    mma8f(sacc[mg][tn], qf[mg][2 * qg    ], kb.x, kb.y);
                    mma8f(sacc[mg][tn], qf[mg][2 * qg + 1], kb.z, kb.w);
                }
            }
        }

        // ---- P = exp(S), row sums ----
        #pragma unroll
        for (int mg = 0; mg < 2; mg++)
            #pragma unroll
            for (int tn = 0; tn < 8; tn++) {
                float p0 = to_tf32(__expf(sacc[mg][tn][0]));
                float p1 = to_tf32(__expf(sacc[mg][tn][1]));
                float p2 = to_tf32(__expf(sacc[mg][tn][2]));
                float p3 = to_tf32(__expf(sacc[mg][tn][3]));
                lsum[mg][0] += p0 + p1;
                lsum[mg][1] += p2 + p3;
                sacc[mg][tn][0] = p0; sacc[mg][tn][1] = p1;
                sacc[mg][tn][2] = p2; sacc[mg][tn][3] = p3;
            }

        // ---- O += P @ V : A-frag = (e0, e2, e1, e3), no shuffles ----
        #pragma unroll
        for (int j = 0; j < 8; j++) {
            #pragma unroll
            for (int dnp = 0; dnp < 4; dnp++) {
                float4 vb = *(const float4*)(Vp + (j * 4 + dnp) * 128 + lane * 4);
                #pragma unroll
                for (int mg = 0; mg < 2; mg++) {
                    const float* p = sacc[mg][j];
                    mma8e(oacc[mg][2 * dnp    ], p[0], p[2], p[1], p[3], vb.x, vb.y);
                    mma8e(oacc[mg][2 * dnp + 1], p[0], p[2], p[1], p[3], vb.z, vb.w);
                }
            }
        }
        if (++buf == 3) buf = 0;
    }

    // ---- finalize l (quad reduce) and write out ----
    #pragma unroll
    for (int mg = 0; mg < 2; mg++)
        #pragma unroll
        for (int r = 0; r < 2; r++) {
            lsum[mg][r] += __shfl_xor_sync(0xffffffffu, lsum[mg][r], 1);
            lsum[mg][r] += __shfl_xor_sync(0xffffffffu, lsum[mg][r], 2);
        }

    const int b = bh >> 4, h = bh & (HHEADS - 1);
    #pragma unroll
    for (int mg = 0; mg < 2; mg++) {
        const float inv0 = 1.f / lsum[mg][0];
        const float inv1 = 1.f / lsum[mg][1];
        float* o0 = out + ((size_t)b * SSEQ + s0 + wid * 32 + mg * 16 + gid) * EEMB + h * DKK;
        float* o1 = o0 + 8 * EEMB;
        #pragma unroll
        for (int dn = 0; dn < 8; dn++) {
            int c = dn * 8 + 2 * tig;
            *(float2*)(o0 + c) = make_float2(oacc[mg][dn][0] * inv0, oacc[mg][dn][1] * inv0);
            *(float2*)(o1 + c) = make_float2(oacc[mg][dn][2] * inv1, oacc[mg][dn][3] * inv1);
        }
    }
}

// ===================== launch =====================
extern "C" void kernel_launch(void* const* d_in, const int* in_sizes, int n_in,
                              void* d_out, int out_size)
{
    const float* x     = (const float*)d_in[0];
    const float* Wk    = (const float*)d_in[1];
    const float* Wv    = (const float*)d_in[2];
    const float* Wq    = (const float*)d_in[3];
    const float* theta = (const float*)d_in[4];
    float* out = (float*)d_out;

    cudaFuncSetAttribute(proj_mma, cudaFuncAttributeMaxDynamicSharedMemorySize, PJ_SMEM);
    cudaFuncSetAttribute(attn_mma, cudaFuncAttributeMaxDynamicSharedMemorySize, AT_SMEM);

    prep_kernel<<<dim3(4096, 4), 256>>>(x, Wk, Wv, Wq);

    dim3 gp(3 * EEMB / 128, (BBATCH * SSEQ) / 128);   // (24, 32)
    proj_mma<<<gp, 256, PJ_SMEM>>>(theta);

    dim3 ga(SSEQ / 256, BBATCH * HHEADS);              // (8, 32)
    attn_mma<<<ga, 256, AT_SMEM>>>(out);
}

// round 10
// speedup vs baseline: 2.0743x; 1.0084x over previous
#include <cuda_runtime.h>
#include <math.h>
#include <stdint.h>

#define BBATCH 2
#define SSEQ 2048
#define EEMB 1024
#define HHEADS 16
#define DKK 64
#define BHS (BBATCH*HHEADS*SSEQ)

// Scratch
__device__ float g_xi[4096*1024];      // x: [m>>7][k>>5][(g7*4+ks2) 32 blocks][128]  (16KB per (rowblk,chunk))
__device__ float g_wi[3][1024*1024];   // W: [n>>7][k>>4][ng15 16 blocks][128]        (16KB per (colblk, 32k-chunk))
__device__ float g_k[BHS*DKK];         // K: [bh][tile][qg4][key>>3][lane32][comp4], keys PERMUTED in 8-groups
__device__ float g_v[BHS*DKK];         // V: [bh][tile][j8][dnp4][lane32][comp4]
__device__ float g_q[BHS*DKK];         // Q: natural [bh][s][d]

// ---------------- helpers ----------------
__device__ __forceinline__ float to_tf32(float x){
    float r; asm("cvt.rna.tf32.f32 %0, %1;" : "=f"(r) : "f"(x)); return r;
}
__device__ __forceinline__ void rnd4(float4& v){
    v.x = to_tf32(v.x); v.y = to_tf32(v.y); v.z = to_tf32(v.z); v.w = to_tf32(v.w);
}
__device__ __forceinline__ void mma8(float* d,
                                     uint32_t a0, uint32_t a1, uint32_t a2, uint32_t a3,
                                     uint32_t b0, uint32_t b1)
{
    asm volatile("mma.sync.aligned.m16n8k8.row.col.f32.tf32.tf32.f32 "
        "{%0,%1,%2,%3}, {%4,%5,%6,%7}, {%8,%9}, {%0,%1,%2,%3};"
        : "+f"(d[0]), "+f"(d[1]), "+f"(d[2]), "+f"(d[3])
        : "r"(a0), "r"(a1), "r"(a2), "r"(a3), "r"(b0), "r"(b1));
}
#define U(x) __float_as_uint(x)
__device__ __forceinline__ void mma8f(float* d, const float4& a, float b0, float b1){
    mma8(d, U(a.x), U(a.y), U(a.z), U(a.w), U(b0), U(b1));
}
__device__ __forceinline__ void mma8e(float* d, float e0, float e1, float e2, float e3,
                                      float b0, float b1){
    mma8(d, U(e0), U(e1), U(e2), U(e3), U(b0), U(b1));
}
__device__ __forceinline__ uint32_t smem_u32(const void* p){
    uint32_t a;
    asm("{ .reg .u64 t; cvta.to.shared.u64 t, %1; cvt.u32.u64 %0, t; }" : "=r"(a) : "l"(p));
    return a;
}

#define MBAR_INIT(a, c) asm volatile("mbarrier.init.shared.b64 [%0], %1;" :: "r"(a), "r"(c) : "memory")
#define MBAR_EXPECT(a, bytes) \
    asm volatile("mbarrier.arrive.expect_tx.shared.b64 _, [%0], %1;" :: "r"(a), "r"(bytes) : "memory")
#define BULK_G2S(dst, src, bytes, mbar) \
    asm volatile("cp.async.bulk.shared::cta.global.mbarrier::complete_tx::bytes [%0], [%1], %2, [%3];" \
        :: "r"(dst), "l"(src), "r"(bytes), "r"(mbar) : "memory")

#define MBAR_WAIT(mbar, par) do {                                            \
    uint32_t _m = (mbar); uint32_t _p = (par); uint32_t _done;               \
    asm volatile("{ .reg .pred p; mbarrier.try_wait.parity.acquire.cta.shared::cta.b64 p, [%1], %2; selp.b32 %0,1,0,p; }" \
        : "=r"(_done) : "r"(_m), "r"(_p) : "memory");                        \
    if (!_done) {                                                            \
        asm volatile("{ .reg .pred P1; WL%=: mbarrier.try_wait.parity.acquire.cta.shared::cta.b64 P1, [%0], %1, 0x989680; @P1 bra.uni WD%=; bra.uni WL%=; WD%=: }" \
            :: "r"(_m), "r"(_p) : "memory");                                 \
    }                                                                        \
} while(0)

// =====================================================================
// Prep: interleave + tf32-round x and W (bulk-copy-friendly block order).
// =====================================================================
__global__ __launch_bounds__(256)
void prep_kernel(const float* __restrict__ x, const float* __restrict__ Wk,
                 const float* __restrict__ Wv, const float* __restrict__ Wq)
{
    const int gi = blockIdx.x * 256 + threadIdx.x;
    if (blockIdx.y == 0) {
        if (gi < 4096*1024/4) {
            int m = gi >> 8, j = gi & 255;           // k = 4j..4j+3
            float4 v = ((const float4*)x)[gi];
            rnd4(v);
            int rb = m >> 7, ch = j >> 3;
            int g7 = (m >> 4) & 7, ks2 = (j >> 1) & 3;
            int gm = m & 15, half = j & 1;
            int base = (((rb * 32 + ch) * 32) + g7 * 4 + ks2) * 128
                     + (gm & 7) * 16 + ((gm >> 3) & 1) + 2 * half;
            g_xi[base     ] = v.x;
            g_xi[base +  4] = v.y;
            g_xi[base +  8] = v.z;
            g_xi[base + 12] = v.w;
        }
    } else {
        if (gi < 1024*1024/4) {
            const float* W = (blockIdx.y == 1) ? Wk : (blockIdx.y == 2) ? Wv : Wq;
            float* dst = g_wi[blockIdx.y - 1];
            int n = gi >> 8, j = gi & 255;
            float4 v = ((const float4*)W)[gi];
            rnd4(v);
            int nb = n >> 7, kg = j >> 2, ng15 = (n >> 3) & 15;   // kg in [0,64)
            int base = (((nb * 64 + kg) * 16) + ng15) * 128       // FIXED: nb stride = 64 kg-blocks
                     + (n & 7) * 16 + (j & 3);
            dst[base     ] = v.x;
            dst[base +  4] = v.y;
            dst[base +  8] = v.z;
            dst[base + 12] = v.w;
        }
    }
}

// =====================================================================
// Merged projection, 3-stage bulk-copy pipeline (1 expect + 2 bulks / chunk).
// smem floats: A[s] @ s*4096 ; W[s] @ 12288 + s*4096 ; mbars @ byte 98304
// =====================================================================
#define PJ_SMEM (98304 + 32)

__global__ __launch_bounds__(256, 2)
void proj_mma(const float* __restrict__ theta)
{
    extern __shared__ float sm[];
    const uint32_t sb = smem_u32(sm);
    const uint32_t mb0 = sb + 98304;
    const int tid = threadIdx.x;
    const int wid = tid >> 5, lane = tid & 31;
    const int gid = lane >> 2, tig = lane & 3;
    const int wm = wid >> 1, wn = wid & 1;
    const int row0 = blockIdx.y * 128;
    const int col0g = blockIdx.x * 128;
    const int mode = col0g >> 10;
    const int coll = col0g & 1023;

    float acc[2][8][4];
    #pragma unroll
    for (int i = 0; i < 2; i++)
        #pragma unroll
        for (int j = 0; j < 8; j++)
            #pragma unroll
            for (int e = 0; e < 4; e++) acc[i][j][e] = 0.f;

    const float* Ab = g_xi + (size_t)blockIdx.y * 32 * 4096;              // rb = blockIdx.y
    const float* Wb = g_wi[mode] + (size_t)(coll >> 7) * 131072;          // FIXED: nb stride = 64*2048

    auto issue = [&](int ch, int b) {
        uint32_t mbar = mb0 + b * 8;
        MBAR_EXPECT(mbar, 32768u);
        BULK_G2S(sb + b * 4096 * 4,           Ab + (size_t)ch * 4096, 16384u, mbar);
        BULK_G2S(sb + (12288 + b * 4096) * 4, Wb + (size_t)ch * 4096, 16384u, mbar);
    };

    if (tid == 0) { MBAR_INIT(mb0, 1); MBAR_INIT(mb0 + 8, 1); MBAR_INIT(mb0 + 16, 1); }
    __syncthreads();
    if (tid == 0) { issue(0, 0); issue(1, 1); }

    int buf = 0, par = 0;
    #pragma unroll 1
    for (int ch = 0; ch < 32; ch++) {
        MBAR_WAIT(mb0 + buf * 8, par);
        __syncthreads();
        if (ch + 2 < 32 && tid == 0) {
            int nb = buf + 2; if (nb >= 3) nb -= 3;
            issue(ch + 2, nb);
        }

        const float* As = sm + buf * 4096;
        const float* Ws = sm + 12288 + buf * 4096;
        #pragma unroll
        for (int qg = 0; qg < 2; qg++) {
            float4 af[2][2];
            #pragma unroll
            for (int tm = 0; tm < 2; tm++)
                #pragma unroll
                for (int kso = 0; kso < 2; kso++)
                    af[tm][kso] = *(const float4*)(As + ((wm*2+tm)*4 + qg*2+kso) * 128 + lane * 4);
            #pragma unroll
            for (int tn = 0; tn < 8; tn++) {
                float4 wb = *(const float4*)(Ws + (qg*16 + wn*8 + tn) * 128 + lane * 4);
                #pragma unroll
                for (int tm = 0; tm < 2; tm++) {
                    mma8f(acc[tm][tn], af[tm][0], wb.x, wb.y);
                    mma8f(acc[tm][tn], af[tm][1], wb.z, wb.w);
                }
            }
        }
        if (++buf == 3) { buf = 0; par ^= 1; }
    }

    // epilogue scatter (tf32-rounded). K gets key-permuted columns.
    #pragma unroll
    for (int tm = 0; tm < 2; tm++) {
        #pragma unroll
        for (int tn = 0; tn < 8; tn++) {
            #pragma unroll
            for (int e = 0; e < 4; e++) {
                int m = row0 + wm * 32 + tm * 16 + gid + (e >= 2 ? 8 : 0);
                int nn = coll + wn * 64 + tn * 8 + 2 * tig + (e & 1);
                int b = m >> 11, s = m & (SSEQ - 1);
                int h = nn >> 6, d = nn & (DKK - 1);
                int bh = b * HHEADS + h;
                float v = acc[tm][tn][e];
                size_t idx;
                if (mode == 0) {
                    int tile = s >> 6, ks = s & 63;
                    int tnk = ks >> 3, kk = ks & 7;
                    int col = ((kk & 3) << 1) | (kk >> 2);   // key permutation
                    int qg = d >> 4, dk = d & 15;
                    idx = (size_t)bh * 131072 + tile * 4096
                        + (((qg * 8 + tnk) * 32 + col * 4 + (dk & 3)) << 2) + (dk >> 2);
                } else if (mode == 1) {
                    int tile = s >> 6, ks = s & 63;
                    int j = ks >> 3, kk = ks & 7;
                    int dn = d >> 3, gidd = d & 7;
                    idx = (size_t)bh * 131072 + tile * 4096
                        + (((j * 4 + (dn >> 1)) * 32 + gidd * 4 + (kk & 3)) << 2)
                        + ((dn & 1) * 2 + (kk >> 2));
                } else {
                    v = cosf(v + __ldg(&theta[d])) * 0.125f;
                    idx = ((size_t)bh * SSEQ + s) * DKK + d;
                }
                float* dst = (mode == 0) ? g_k : (mode == 1) ? g_v : g_q;
                dst[idx] = to_tf32(v);
            }
        }
    }
}

// =====================================================================
// Attention: CTA = 256q x 1 head, 8 warps, warp = 32q x 64keys x 64d.
// 3-stage bulk-copy pipeline, no shuffles (key permutation trick).
// smem floats: K[s] @ s*4096 ; V[s] @ 12288 + s*4096 ; mbars @ byte 98304
// =====================================================================
#define AT_SMEM (98304 + 32)

__global__ __launch_bounds__(256, 1)
void attn_mma(float* __restrict__ out)
{
    extern __shared__ float sm[];
    const uint32_t sb = smem_u32(sm);
    const uint32_t mb0 = sb + 98304;
    const int tid = threadIdx.x;
    const int wid = tid >> 5, lane = tid & 31;
    const int gid = lane >> 2, tig = lane & 3;
    const int bh = blockIdx.y;
    const int s0 = blockIdx.x * 256;

    // ---- Q fragments in registers: 2 m-groups x 8 k-steps ----
    float4 qf[2][8];
    #pragma unroll
    for (int mg = 0; mg < 2; mg++) {
        const float* qb = g_q + ((size_t)bh * SSEQ + s0 + wid * 32 + mg * 16) * DKK;
        #pragma unroll
        for (int ks = 0; ks < 8; ks++) {
            int c = 8 * ks + tig;
            qf[mg][ks] = make_float4(qb[gid * DKK + c],     qb[(gid + 8) * DKK + c],
                                     qb[gid * DKK + c + 4], qb[(gid + 8) * DKK + c + 4]);
        }
    }

    const float* kg = g_k + (size_t)bh * 131072;
    const float* vg = g_v + (size_t)bh * 131072;

    auto issue = [&](int t, int b) {
        uint32_t mbar = mb0 + b * 8;
        MBAR_EXPECT(mbar, 32768u);
        BULK_G2S(sb + b * 4096 * 4,           kg + (size_t)t * 4096, 16384u, mbar);
        BULK_G2S(sb + (12288 + b * 4096) * 4, vg + (size_t)t * 4096, 16384u, mbar);
    };

    if (tid == 0) { MBAR_INIT(mb0, 1); MBAR_INIT(mb0 + 8, 1); MBAR_INIT(mb0 + 16, 1); }
    __syncthreads();
    if (tid == 0) { issue(0, 0); issue(1, 1); }

    float oacc[2][8][4];
    #pragma unroll
    for (int mg = 0; mg < 2; mg++)
        #pragma unroll
        for (int dn = 0; dn < 8; dn++)
            #pragma unroll
            for (int e = 0; e < 4; e++) oacc[mg][dn][e] = 0.f;
    float lsum[2][2] = {{0.f, 0.f}, {0.f, 0.f}};

    int buf = 0, par = 0;
    #pragma unroll 1
    for (int t = 0; t < 32; t++) {
        MBAR_WAIT(mb0 + buf * 8, par);
        __syncthreads();
        if (t + 2 < 32 && tid == 0) {
            int nb = buf + 2; if (nb >= 3) nb -= 3;
            issue(t + 2, nb);
        }

        const float* Kp = sm + buf * 4096;
        const float* Vp = sm + 12288 + buf * 4096;

        // ---- S = Q @ K^T (key-permuted columns) ----
        float sacc[2][8][4];
        #pragma unroll
        for (int mg = 0; mg < 2; mg++)
            #pragma unroll
            for (int tn = 0; tn < 8; tn++)
                #pragma unroll
                for (int e = 0; e < 4; e++) sacc[mg][tn][e] = 0.f;

        #pragma unroll
        for (int qg = 0; qg < 4; qg++) {
            #pragma unroll
            for (int tn = 0; tn < 8; tn++) {
                float4 kb = *(const float4*)(Kp + (qg * 8 + tn) * 128 + lane * 4);
                #pragma unroll
                for (int mg = 0; mg < 2; mg++) {
                    mma8f(sacc[mg][tn], qf[mg][2 * qg    ], kb.x, kb.y);
                    mma8f(sacc[mg][tn], qf[mg][2 * qg + 1], kb.z, kb.w);
                }
            }
        }

        // ---- P = exp(S), row sums ----
        #pragma unroll
        for (int mg = 0; mg < 2; mg++)
            #pragma unroll
            for (int tn = 0; tn < 8; tn++) {
                float p0 = to_tf32(__expf(sacc[mg][tn][0]));
                float p1 = to_tf32(__expf(sacc[mg][tn][1]));
                float p2 = to_tf32(__expf(sacc[mg][tn][2]));
                float p3 = to_tf32(__expf(sacc[mg][tn][3]));
                lsum[mg][0] += p0 + p1;
                lsum[mg][1] += p2 + p3;
                sacc[mg][tn][0] = p0; sacc[mg][tn][1] = p1;
                sacc[mg][tn][2] = p2; sacc[mg][tn][3] = p3;
            }

        // ---- O += P @ V : A-frag = (e0, e2, e1, e3), no shuffles ----
        #pragma unroll
        for (int j = 0; j < 8; j++) {
            #pragma unroll
            for (int dnp = 0; dnp < 4; dnp++) {
                float4 vb = *(const float4*)(Vp + (j * 4 + dnp) * 128 + lane * 4);
                #pragma unroll
                for (int mg = 0; mg < 2; mg++) {
                    const float* p = sacc[mg][j];
                    mma8e(oacc[mg][2 * dnp    ], p[0], p[2], p[1], p[3], vb.x, vb.y);
                    mma8e(oacc[mg][2 * dnp + 1], p[0], p[2], p[1], p[3], vb.z, vb.w);
                }
            }
        }
        if (++buf == 3) { buf = 0; par ^= 1; }
    }

    // ---- finalize l (quad reduce) and write out ----
    #pragma unroll
    for (int mg = 0; mg < 2; mg++)
        #pragma unroll
        for (int r = 0; r < 2; r++) {
            lsum[mg][r] += __shfl_xor_sync(0xffffffffu, lsum[mg][r], 1);
            lsum[mg][r] += __shfl_xor_sync(0xffffffffu, lsum[mg][r], 2);
        }

    const int b = bh >> 4, h = bh & (HHEADS - 1);
    #pragma unroll
    for (int mg = 0; mg < 2; mg++) {
        const float inv0 = 1.f / lsum[mg][0];
        const float inv1 = 1.f / lsum[mg][1];
        float* o0 = out + ((size_t)b * SSEQ + s0 + wid * 32 + mg * 16 + gid) * EEMB + h * DKK;
        float* o1 = o0 + 8 * EEMB;
        #pragma unroll
        for (int dn = 0; dn < 8; dn++) {
            int c = dn * 8 + 2 * tig;
            *(float2*)(o0 + c) = make_float2(oacc[mg][dn][0] * inv0, oacc[mg][dn][1] * inv0);
            *(float2*)(o1 + c) = make_float2(oacc[mg][dn][2] * inv1, oacc[mg][dn][3] * inv1);
        }
    }
}

// ===================== launch =====================
extern "C" void kernel_launch(void* const* d_in, const int* in_sizes, int n_in,
                              void* d_out, int out_size)
{
    const float* x     = (const float*)d_in[0];
    const float* Wk    = (const float*)d_in[1];
    const float* Wv    = (const float*)d_in[2];
    const float* Wq    = (const float*)d_in[3];
    const float* theta = (const float*)d_in[4];
    float* out = (float*)d_out;

    cudaFuncSetAttribute(proj_mma, cudaFuncAttributeMaxDynamicSharedMemorySize, PJ_SMEM);
    cudaFuncSetAttribute(attn_mma, cudaFuncAttributeMaxDynamicSharedMemorySize, AT_SMEM);

    prep_kernel<<<dim3(4096, 4), 256>>>(x, Wk, Wv, Wq);

    dim3 gp(3 * EEMB / 128, (BBATCH * SSEQ) / 128);   // (24, 32)
    proj_mma<<<gp, 256, PJ_SMEM>>>(theta);

    dim3 ga(SSEQ / 256, BBATCH * HHEADS);              // (8, 32)
    attn_mma<<<ga, 256, AT_SMEM>>>(out);
}

// round 11
// speedup vs baseline: 3.4264x; 1.6519x over previous
#include <cuda_runtime.h>
#include <cuda_fp16.h>
#include <math.h>
#include <stdint.h>

#define BBATCH 2
#define SSEQ 2048
#define EEMB 1024
#define HHEADS 16
#define DKK 64
#define BHS (BBATCH*HHEADS*SSEQ)

// Scratch (all fp16, fragment-interleaved for single-LDS.128 operand fetch)
__device__ unsigned short g_xi[4096*1024];    // x: [m>>7][k>>6][(g*4+ks)32][lane32][comp4] b32 words
__device__ unsigned short g_wi[3][1024*1024]; // W: [n>>7][k>>6][(ng*2+sp)32][lane32][comp4]
__device__ unsigned short g_k[BHS*DKK];       // K: [bh][tile64][(ng*2+sp)16][lane32][comp4]
__device__ unsigned short g_v[BHS*DKK];       // V: [bh][tile64][(dn*2+kcp)16][lane32][comp4]
__device__ unsigned short g_q[BHS*DKK];       // Q: natural [bh][s][d]

// ---------------- helpers ----------------
__device__ __forceinline__ void mma16(float* d, uint32_t a0, uint32_t a1,
                                      uint32_t a2, uint32_t a3,
                                      uint32_t b0, uint32_t b1)
{
    asm volatile("mma.sync.aligned.m16n8k16.row.col.f32.f16.f16.f32 "
        "{%0,%1,%2,%3}, {%4,%5,%6,%7}, {%8,%9}, {%0,%1,%2,%3};"
        : "+f"(d[0]), "+f"(d[1]), "+f"(d[2]), "+f"(d[3])
        : "r"(a0), "r"(a1), "r"(a2), "r"(a3), "r"(b0), "r"(b1));
}
__device__ __forceinline__ void mma16v(float* d, const uint4& a, uint32_t b0, uint32_t b1){
    mma16(d, a.x, a.y, a.z, a.w, b0, b1);
}
__device__ __forceinline__ uint32_t packh2(float a, float b){
    __half2 h = __floats2half2_rn(a, b);
    return *(uint32_t*)&h;
}
__device__ __forceinline__ uint32_t smem_u32(const void* p){
    uint32_t a;
    asm("{ .reg .u64 t; cvta.to.shared.u64 t, %1; cvt.u32.u64 %0, t; }" : "=r"(a) : "l"(p));
    return a;
}

#define MBAR_INIT(a, c) asm volatile("mbarrier.init.shared.b64 [%0], %1;" :: "r"(a), "r"(c) : "memory")
#define MBAR_EXPECT(a, bytes) \
    asm volatile("mbarrier.arrive.expect_tx.shared.b64 _, [%0], %1;" :: "r"(a), "r"(bytes) : "memory")
#define BULK_G2S(dst, src, bytes, mbar) \
    asm volatile("cp.async.bulk.shared::cta.global.mbarrier::complete_tx::bytes [%0], [%1], %2, [%3];" \
        :: "r"(dst), "l"(src), "r"(bytes), "r"(mbar) : "memory")

#define MBAR_WAIT(mbar, par) do {                                            \
    uint32_t _m = (mbar); uint32_t _p = (par); uint32_t _done;               \
    asm volatile("{ .reg .pred p; mbarrier.try_wait.parity.acquire.cta.shared::cta.b64 p, [%1], %2; selp.b32 %0,1,0,p; }" \
        : "=r"(_done) : "r"(_m), "r"(_p) : "memory");                        \
    if (!_done) {                                                            \
        asm volatile("{ .reg .pred P1; WL%=: mbarrier.try_wait.parity.acquire.cta.shared::cta.b64 P1, [%0], %1, 0x989680; @P1 bra.uni WD%=; bra.uni WL%=; WD%=: }" \
            :: "r"(_m), "r"(_p) : "memory");                                 \
    }                                                                        \
} while(0)

// =====================================================================
// Prep: fp16-round + fragment-interleave x and W.
// comp encodings (per b32 word of 2 fp16, low half = even k):
//   x: comp = rowhalf + 2*khalf     (a-frag order a0,a1,a2,a3)
//   W: comp = kso*2 + khalf         (b-frags for ksteps 2sp, 2sp+1)
// =====================================================================
__global__ __launch_bounds__(256)
void prep_kernel(const float* __restrict__ x, const float* __restrict__ Wk,
                 const float* __restrict__ Wv, const float* __restrict__ Wq)
{
    const int gi = blockIdx.x * 256 + threadIdx.x;
    if (blockIdx.y == 0) {
        if (gi < 4096*1024/4) {
            int m = gi >> 8, j = gi & 255;           // k = 4j..4j+3
            float4 v = ((const float4*)x)[gi];
            int rb = m >> 7, ch = j >> 4;
            int g = (m >> 4) & 7, ks = (j >> 2) & 3;
            int r16 = m & 15, gid = r16 & 7, rh = r16 >> 3;
            int k16 = (4 * j) & 15, tig = (k16 & 7) >> 1, khalf = k16 >> 3;
            int word = (((rb * 16 + ch) * 32) + g * 4 + ks) * 128
                     + (gid * 4 + tig) * 4 + (rh + 2 * khalf);
            *(__half2*)(g_xi + 2 * word)       = __floats2half2_rn(v.x, v.y);
            *(__half2*)(g_xi + 2 * (word + 4)) = __floats2half2_rn(v.z, v.w);
        }
    } else {
        if (gi < 1024*1024/4) {
            const float* W = (blockIdx.y == 1) ? Wk : (blockIdx.y == 2) ? Wv : Wq;
            unsigned short* dst = g_wi[blockIdx.y - 1];
            int n = gi >> 8, j = gi & 255;
            float4 v = ((const float4*)W)[gi];
            int nb = n >> 7, ch = j >> 4;
            int ng = (n >> 3) & 15, gid = n & 7;
            int ks = (j >> 2) & 3, sp = ks >> 1, kso = ks & 1;
            int k16 = (4 * j) & 15, tig = (k16 & 7) >> 1, khalf = k16 >> 3;
            int word = (((nb * 16 + ch) * 32) + ng * 2 + sp) * 128
                     + (gid * 4 + tig) * 4 + (kso * 2 + khalf);
            *(__half2*)(dst + 2 * word)       = __floats2half2_rn(v.x, v.y);
            *(__half2*)(dst + 2 * (word + 4)) = __floats2half2_rn(v.z, v.w);
        }
    }
}

// =====================================================================
// Merged projection: fp16 m16n8k16, chunk = 64 k (16 chunks), 3-stage bulk.
// smem bytes: A[s] @ s*16384 ; W[s] @ 49152 + s*16384 ; mbars @ 98304
// =====================================================================
#define PJ_SMEM (98304 + 32)

__global__ __launch_bounds__(256, 2)
void proj_mma(const float* __restrict__ theta)
{
    extern __shared__ char smc[];
    const uint32_t sb = smem_u32(smc);
    const uint32_t mb0 = sb + 98304;
    const int tid = threadIdx.x;
    const int wid = tid >> 5, lane = tid & 31;
    const int gid = lane >> 2, tig = lane & 3;
    const int wm = wid >> 1, wn = wid & 1;
    const int row0 = blockIdx.y * 128;
    const int col0g = blockIdx.x * 128;
    const int mode = col0g >> 10;
    const int coll = col0g & 1023;
    const int nb = coll >> 7;

    float acc[2][8][4];
    #pragma unroll
    for (int i = 0; i < 2; i++)
        #pragma unroll
        for (int j = 0; j < 8; j++)
            #pragma unroll
            for (int e = 0; e < 4; e++) acc[i][j][e] = 0.f;

    const unsigned short* Ab = g_xi + (size_t)blockIdx.y * 131072;   // rb*16*8192
    const unsigned short* Wb = g_wi[mode] + (size_t)nb * 131072;

    auto issue = [&](int ch, int b) {
        uint32_t mbar = mb0 + b * 8;
        MBAR_EXPECT(mbar, 32768u);
        BULK_G2S(sb + b * 16384,         (const void*)(Ab + ch * 8192), 16384u, mbar);
        BULK_G2S(sb + 49152 + b * 16384, (const void*)(Wb + ch * 8192), 16384u, mbar);
    };

    if (tid == 0) { MBAR_INIT(mb0, 1); MBAR_INIT(mb0 + 8, 1); MBAR_INIT(mb0 + 16, 1); }
    __syncthreads();
    if (tid == 0) { issue(0, 0); issue(1, 1); }

    int buf = 0, par = 0;
    #pragma unroll 1
    for (int ch = 0; ch < 16; ch++) {
        MBAR_WAIT(mb0 + buf * 8, par);
        __syncthreads();
        if (ch + 2 < 16 && tid == 0) {
            int nbuf = buf + 2; if (nbuf >= 3) nbuf -= 3;
            issue(ch + 2, nbuf);
        }

        const uint4* As = (const uint4*)(smc + buf * 16384);
        const uint4* Ws = (const uint4*)(smc + 49152 + buf * 16384);
        #pragma unroll
        for (int sp = 0; sp < 2; sp++) {
            uint4 af[2][2];
            #pragma unroll
            for (int tm = 0; tm < 2; tm++)
                #pragma unroll
                for (int kso = 0; kso < 2; kso++)
                    af[tm][kso] = As[((2*wm+tm)*4 + 2*sp+kso) * 32 + lane];
            #pragma unroll
            for (int tn = 0; tn < 8; tn++) {
                uint4 wb = Ws[((wn*8+tn)*2 + sp) * 32 + lane];
                #pragma unroll
                for (int tm = 0; tm < 2; tm++) {
                    mma16v(acc[tm][tn], af[tm][0], wb.x, wb.y);
                    mma16v(acc[tm][tn], af[tm][1], wb.z, wb.w);
                }
            }
        }
        if (++buf == 3) { buf = 0; par ^= 1; }
    }

    // epilogue: fp16 scatter to K/V fragment layouts, Q natural (+cos)
    #pragma unroll
    for (int tm = 0; tm < 2; tm++) {
        #pragma unroll
        for (int tn = 0; tn < 8; tn++) {
            #pragma unroll
            for (int e = 0; e < 4; e++) {
                int m = row0 + wm * 32 + tm * 16 + gid + (e >= 2 ? 8 : 0);
                int nn = coll + wn * 64 + tn * 8 + 2 * tig + (e & 1);
                int b = m >> 11, s = m & (SSEQ - 1);
                int h = nn >> 6, d = nn & (DKK - 1);
                int bh = b * HHEADS + h;
                float v = acc[tm][tn][e];
                size_t idx;
                if (mode == 0) {
                    // K: key = s&63 in tile s>>6; b-frag layout over (key, d)
                    int tile = s >> 6, key = s & 63;
                    int ng = key >> 3, gidk = key & 7;
                    int ks = d >> 4, sp = ks >> 1, kso = ks & 1;
                    int k16 = d & 15, khalf = k16 >> 3, tigk = (k16 & 7) >> 1, kodd = d & 1;
                    int word = ((ng * 2 + sp) * 32 + gidk * 4 + tigk) * 4 + (kso * 2 + khalf);
                    idx = ((size_t)(bh * 32 + tile) * 2048 + word) * 2 + kodd;
                } else if (mode == 1) {
                    // V: b-frag layout over (d=n, key=k)
                    int tile = s >> 6, key = s & 63;
                    int dn = d >> 3, gidd = d & 7;
                    int kc = key >> 4, kcp = kc >> 1, kco = kc & 1;
                    int key16 = key & 15, khalf = key16 >> 3, tigv = (key16 & 7) >> 1, kodd = key & 1;
                    int word = ((dn * 2 + kcp) * 32 + gidd * 4 + tigv) * 4 + (kco * 2 + khalf);
                    idx = ((size_t)(bh * 32 + tile) * 2048 + word) * 2 + kodd;
                } else {
                    v = cosf(v + __ldg(&theta[d])) * 0.125f;
                    idx = ((size_t)bh * SSEQ + s) * DKK + d;
                }
                unsigned short* dst = (mode == 0) ? g_k : (mode == 1) ? g_v : g_q;
                __half hv = __float2half_rn(v);
                dst[idx] = *(unsigned short*)&hv;
            }
        }
    }
}

// =====================================================================
// Attention: CTA = 256q x 1 head, 8 warps, warp = 32q x 64keys x 64d.
// fp16 m16n8k16; P transpose is free (c0c1 pair == A-operand f16x2).
// smem bytes: K[s] @ s*8192 ; V[s] @ 24576 + s*8192 ; mbars @ 49152
// =====================================================================
#define AT_SMEM (49152 + 32)

__global__ __launch_bounds__(256, 1)
void attn_mma(float* __restrict__ out)
{
    extern __shared__ char smc[];
    const uint32_t sb = smem_u32(smc);
    const uint32_t mb0 = sb + 49152;
    const int tid = threadIdx.x;
    const int wid = tid >> 5, lane = tid & 31;
    const int gid = lane >> 2, tig = lane & 3;
    const int bh = blockIdx.y;
    const int s0 = blockIdx.x * 256;

    // ---- Q fragments in registers: 2 m-groups x 4 k-steps (a-frags) ----
    uint4 qf[2][4];
    #pragma unroll
    for (int mg = 0; mg < 2; mg++) {
        const unsigned short* qb = g_q + ((size_t)bh * SSEQ + s0 + wid * 32 + mg * 16) * DKK;
        #pragma unroll
        for (int ks = 0; ks < 4; ks++) {
            int c = 16 * ks + 2 * tig;
            qf[mg][ks].x = *(const uint32_t*)(qb + gid * DKK + c);
            qf[mg][ks].y = *(const uint32_t*)(qb + (gid + 8) * DKK + c);
            qf[mg][ks].z = *(const uint32_t*)(qb + gid * DKK + c + 8);
            qf[mg][ks].w = *(const uint32_t*)(qb + (gid + 8) * DKK + c + 8);
        }
    }

    const unsigned short* kg = g_k + (size_t)bh * 131072;   // 32 tiles * 4096 u16
    const unsigned short* vg = g_v + (size_t)bh * 131072;

    auto issue = [&](int t, int b) {
        uint32_t mbar = mb0 + b * 8;
        MBAR_EXPECT(mbar, 16384u);
        BULK_G2S(sb + b * 8192,         (const void*)(kg + t * 4096), 8192u, mbar);
        BULK_G2S(sb + 24576 + b * 8192, (const void*)(vg + t * 4096), 8192u, mbar);
    };

    if (tid == 0) { MBAR_INIT(mb0, 1); MBAR_INIT(mb0 + 8, 1); MBAR_INIT(mb0 + 16, 1); }
    __syncthreads();
    if (tid == 0) { issue(0, 0); issue(1, 1); }

    float oacc[2][8][4];
    #pragma unroll
    for (int mg = 0; mg < 2; mg++)
        #pragma unroll
        for (int dn = 0; dn < 8; dn++)
            #pragma unroll
            for (int e = 0; e < 4; e++) oacc[mg][dn][e] = 0.f;
    float lsum[2][2] = {{0.f, 0.f}, {0.f, 0.f}};

    int buf = 0, par = 0;
    #pragma unroll 1
    for (int t = 0; t < 32; t++) {
        MBAR_WAIT(mb0 + buf * 8, par);
        __syncthreads();
        if (t + 2 < 32 && tid == 0) {
            int nbuf = buf + 2; if (nbuf >= 3) nbuf -= 3;
            issue(t + 2, nbuf);
        }

        const uint4* Kp = (const uint4*)(smc + buf * 8192);
        const uint4* Vp = (const uint4*)(smc + 24576 + buf * 8192);

        // ---- S = Q @ K^T ----
        float sacc[2][8][4];
        #pragma unroll
        for (int mg = 0; mg < 2; mg++)
            #pragma unroll
            for (int tn = 0; tn < 8; tn++)
                #pragma unroll
                for (int e = 0; e < 4; e++) sacc[mg][tn][e] = 0.f;

        #pragma unroll
        for (int sp = 0; sp < 2; sp++) {
            #pragma unroll
            for (int tn = 0; tn < 8; tn++) {
                uint4 kb = Kp[(tn * 2 + sp) * 32 + lane];
                #pragma unroll
                for (int mg = 0; mg < 2; mg++) {
                    mma16v(sacc[mg][tn], qf[mg][2 * sp    ], kb.x, kb.y);
                    mma16v(sacc[mg][tn], qf[mg][2 * sp + 1], kb.z, kb.w);
                }
            }
        }

        // ---- P = exp(S), pack to fp16 pairs, row sums ----
        uint32_t plo[2][8], phi[2][8];
        #pragma unroll
        for (int mg = 0; mg < 2; mg++)
            #pragma unroll
            for (int tn = 0; tn < 8; tn++) {
                float p0 = __expf(sacc[mg][tn][0]);
                float p1 = __expf(sacc[mg][tn][1]);
                float p2 = __expf(sacc[mg][tn][2]);
                float p3 = __expf(sacc[mg][tn][3]);
                lsum[mg][0] += p0 + p1;
                lsum[mg][1] += p2 + p3;
                plo[mg][tn] = packh2(p0, p1);
                phi[mg][tn] = packh2(p2, p3);
            }

        // ---- O += P @ V : A-frags directly from packed S pairs ----
        #pragma unroll
        for (int kcp = 0; kcp < 2; kcp++) {
            #pragma unroll
            for (int dn = 0; dn < 8; dn++) {
                uint4 vb = Vp[(dn * 2 + kcp) * 32 + lane];
                #pragma unroll
                for (int mg = 0; mg < 2; mg++) {
                    mma16(oacc[mg][dn],
                          plo[mg][4*kcp    ], phi[mg][4*kcp    ],
                          plo[mg][4*kcp + 1], phi[mg][4*kcp + 1],
                          vb.x, vb.y);
                    mma16(oacc[mg][dn],
                          plo[mg][4*kcp + 2], phi[mg][4*kcp + 2],
                          plo[mg][4*kcp + 3], phi[mg][4*kcp + 3],
                          vb.z, vb.w);
                }
            }
        }
        if (++buf == 3) { buf = 0; par ^= 1; }
    }

    // ---- finalize l (quad reduce) and write out ----
    #pragma unroll
    for (int mg = 0; mg < 2; mg++)
        #pragma unroll
        for (int r = 0; r < 2; r++) {
            lsum[mg][r] += __shfl_xor_sync(0xffffffffu, lsum[mg][r], 1);
            lsum[mg][r] += __shfl_xor_sync(0xffffffffu, lsum[mg][r], 2);
        }

    const int b = bh >> 4, h = bh & (HHEADS - 1);
    #pragma unroll
    for (int mg = 0; mg < 2; mg++) {
        const float inv0 = 1.f / lsum[mg][0];
        const float inv1 = 1.f / lsum[mg][1];
        float* o0 = out + ((size_t)b * SSEQ + s0 + wid * 32 + mg * 16 + gid) * EEMB + h * DKK;
        float* o1 = o0 + 8 * EEMB;
        #pragma unroll
        for (int dn = 0; dn < 8; dn++) {
            int c = dn * 8 + 2 * tig;
            *(float2*)(o0 + c) = make_float2(oacc[mg][dn][0] * inv0, oacc[mg][dn][1] * inv0);
            *(float2*)(o1 + c) = make_float2(oacc[mg][dn][2] * inv1, oacc[mg][dn][3] * inv1);
        }
    }
}

// ===================== launch =====================
extern "C" void kernel_launch(void* const* d_in, const int* in_sizes, int n_in,
                              void* d_out, int out_size)
{
    const float* x     = (const float*)d_in[0];
    const float* Wk    = (const float*)d_in[1];
    const float* Wv    = (const float*)d_in[2];
    const float* Wq    = (const float*)d_in[3];
    const float* theta = (const float*)d_in[4];
    float* out = (float*)d_out;

    cudaFuncSetAttribute(proj_mma, cudaFuncAttributeMaxDynamicSharedMemorySize, PJ_SMEM);
    cudaFuncSetAttribute(attn_mma, cudaFuncAttributeMaxDynamicSharedMemorySize, AT_SMEM);

    prep_kernel<<<dim3(4096, 4), 256>>>(x, Wk, Wv, Wq);

    dim3 gp(3 * EEMB / 128, (BBATCH * SSEQ) / 128);   // (24, 32)
    proj_mma<<<gp, 256, PJ_SMEM>>>(theta);

    dim3 ga(SSEQ / 256, BBATCH * HHEADS);              // (8, 32)
    attn_mma<<<ga, 256, AT_SMEM>>>(out);
}